// round 8
// baseline (speedup 1.0000x reference)
#include <cuda_runtime.h>
#include <cuda_bf16.h>
#include <stdint.h>

// Problem shape (fixed by the dataset)
#define NNODES   50000
#define DIN      256
#define DH       128

// Device scratch — referenced DIRECTLY from kernels.
__device__ __align__(16) float g_dis[NNODES];          // deg -> rsqrt(deg)
__device__ __align__(16) float g_hs [NNODES * DH];     // scaled h / x1 (aliased)
__device__ __align__(16) float g_acc[NNODES * DH];     // aggregation accumulator
__device__ int g_is64;                                  // edge dtype flag

// ---------------------------------------------------------------------------
// Edge-index dtype probe: JAX default config downcasts int64->int32, but be
// robust to both. int64 data (values < 2^31) has all-odd 32-bit words zero;
// int32 data has random src indices there.
// ---------------------------------------------------------------------------
__global__ void k_detect(const int* __restrict__ ei32) {
    int nz = 0;
#pragma unroll
    for (int i = 1; i < 64; i += 2) nz |= ei32[i];
    g_is64 = (nz == 0) ? 1 : 0;
}

__device__ __forceinline__ int load_idx(const void* ei, long long pos) {
    if (g_is64) return (int)((const long long*)ei)[pos];
    return ((const int*)ei)[pos];
}

// ---------------------------------------------------------------------------
// degree / normalization
// ---------------------------------------------------------------------------
__global__ void k_init_deg(int n) {
    int i = blockIdx.x * blockDim.x + threadIdx.x;
    if (i < n) g_dis[i] = 1.0f;  // self loop
}

__global__ void k_count_deg(const void* __restrict__ ei, int E) {
    int e = blockIdx.x * blockDim.x + threadIdx.x;
    if (e < E) {
        int d = load_idx(ei, (long long)E + e);   // dst in-degree
        atomicAdd(&g_dis[d], 1.0f);
    }
}

__global__ void k_rsqrt(int n) {
    int i = blockIdx.x * blockDim.x + threadIdx.x;
    if (i < n) g_dis[i] = rsqrtf(g_dis[i]);
}

// ---------------------------------------------------------------------------
// GEMM: C = A[M,K] @ W[K,128], epilogue scales rows by dis and writes the
// scaled result to BOTH g_hs and g_acc (acc init = self-loop contribution).
// LAYER2 selects A = g_hs (in-place safe: each block reads only its own
// 128-row slice before the epilogue overwrites it).
// BM=128, BN=128, BK=16, TM=8, TN=8, 256 threads.
// ---------------------------------------------------------------------------
template <int K, bool LAYER2>
__global__ __launch_bounds__(256) void k_gemm_scale(
    const float* __restrict__ Ain, const float* __restrict__ W, int M)
{
    const float* __restrict__ A = LAYER2 ? (const float*)g_hs : Ain;

    __shared__ __align__(16) float As[16][128];   // [k][m]
    __shared__ __align__(16) float Bs[16][128];   // [k][n]

    const int tid = threadIdx.x;
    const int block_row = blockIdx.x * 128;
    const int tcol = (tid & 15) * 8;   // 0..120
    const int trow = (tid >> 4) * 8;   // 0..120

    float accum[8][8];
#pragma unroll
    for (int i = 0; i < 8; i++)
#pragma unroll
        for (int j = 0; j < 8; j++) accum[i][j] = 0.0f;

    for (int k0 = 0; k0 < K; k0 += 16) {
        // Load A tile 128x16 (512 float4), transpose into As[k][m]
#pragma unroll
        for (int i = 0; i < 2; i++) {
            int lin = tid * 2 + i;          // 0..511
            int r   = lin >> 2;             // row in tile 0..127
            int c4  = lin & 3;              // float4 index along K
            int gr  = block_row + r;
            float4 v = make_float4(0.f, 0.f, 0.f, 0.f);
            if (gr < M)
                v = reinterpret_cast<const float4*>(A + (size_t)gr * K + k0)[c4];
            As[c4 * 4 + 0][r] = v.x;
            As[c4 * 4 + 1][r] = v.y;
            As[c4 * 4 + 2][r] = v.z;
            As[c4 * 4 + 3][r] = v.w;
        }
        // Load B tile 16x128 (512 float4)
#pragma unroll
        for (int i = 0; i < 2; i++) {
            int lin = tid * 2 + i;
            int r   = lin >> 5;             // k row 0..15
            int c4  = lin & 31;             // float4 col
            float4 v = reinterpret_cast<const float4*>(W + (size_t)(k0 + r) * 128)[c4];
            reinterpret_cast<float4*>(&Bs[r][0])[c4] = v;
        }
        __syncthreads();

#pragma unroll
        for (int k = 0; k < 16; k++) {
            float4 a0 = reinterpret_cast<const float4*>(&As[k][trow])[0];
            float4 a1 = reinterpret_cast<const float4*>(&As[k][trow])[1];
            float4 b0 = reinterpret_cast<const float4*>(&Bs[k][tcol])[0];
            float4 b1 = reinterpret_cast<const float4*>(&Bs[k][tcol])[1];
            float a[8] = {a0.x, a0.y, a0.z, a0.w, a1.x, a1.y, a1.z, a1.w};
            float b[8] = {b0.x, b0.y, b0.z, b0.w, b1.x, b1.y, b1.z, b1.w};
#pragma unroll
            for (int i = 0; i < 8; i++)
#pragma unroll
                for (int j = 0; j < 8; j++)
                    accum[i][j] = fmaf(a[i], b[j], accum[i][j]);
        }
        __syncthreads();
    }

    // Epilogue: scale by dis[row], store to hs and acc
#pragma unroll
    for (int i = 0; i < 8; i++) {
        int gr = block_row + trow + i;
        if (gr < M) {
            float d = g_dis[gr];
#pragma unroll
            for (int j = 0; j < 8; j += 4) {
                float4 v;
                v.x = accum[i][j + 0] * d;
                v.y = accum[i][j + 1] * d;
                v.z = accum[i][j + 2] * d;
                v.w = accum[i][j + 3] * d;
                size_t off = (size_t)gr * 128 + tcol + j;
                reinterpret_cast<float4*>(g_hs  + off)[0] = v;
                reinterpret_cast<float4*>(g_acc + off)[0] = v;
            }
        }
    }
}

// ---------------------------------------------------------------------------
// Scatter: g_acc[dst] += g_hs[src]. One warp per edge; each lane loads a
// float4 and issues 4 scalar reductions (RED.E.ADD.F32, no return).
// ---------------------------------------------------------------------------
__global__ __launch_bounds__(256) void k_scatter(
    const void* __restrict__ ei, int E)
{
    int idx  = blockIdx.x * blockDim.x + threadIdx.x;
    int e    = idx >> 5;
    int lane = idx & 31;
    if (e >= E) return;
    int s = load_idx(ei, e);
    int d = load_idx(ei, (long long)E + e);
    float4 v = reinterpret_cast<const float4*>(g_hs + (size_t)s * 128)[lane];
    float* p = g_acc + (size_t)d * 128 + lane * 4;
    atomicAdd(p + 0, v.x);
    atomicAdd(p + 1, v.y);
    atomicAdd(p + 2, v.z);
    atomicAdd(p + 3, v.w);
}

// ---------------------------------------------------------------------------
// Finalize layer 1: g_hs = relu(dis[i] * g_acc + b1[j])   (hs is dead; reuse)
// ---------------------------------------------------------------------------
__global__ void k_finalize_relu(const float* __restrict__ b, int M)
{
    int idx = blockIdx.x * blockDim.x + threadIdx.x;   // float4 index
    if (idx >= M * 32) return;
    int i  = idx >> 5;
    int j4 = (idx & 31);
    float d = g_dis[i];
    float4 a = reinterpret_cast<const float4*>(g_acc)[idx];
    float4 bb = reinterpret_cast<const float4*>(b)[j4];
    float4 r;
    r.x = fmaxf(fmaf(d, a.x, bb.x), 0.f);
    r.y = fmaxf(fmaf(d, a.y, bb.y), 0.f);
    r.z = fmaxf(fmaf(d, a.z, bb.z), 0.f);
    r.w = fmaxf(fmaf(d, a.w, bb.w), 0.f);
    reinterpret_cast<float4*>(g_hs)[idx] = r;
}

// Finalize layer 2: out = dis[i]*g_acc + b2[j]  (plain stores into d_out only)
__global__ void k_finalize(const float* __restrict__ b,
                           float* __restrict__ out, int M)
{
    int idx = blockIdx.x * blockDim.x + threadIdx.x;
    if (idx >= M * 32) return;
    int i  = idx >> 5;
    int j4 = (idx & 31);
    float d = g_dis[i];
    float4 a = reinterpret_cast<const float4*>(g_acc)[idx];
    float4 bb = reinterpret_cast<const float4*>(b)[j4];
    float4 r;
    r.x = fmaf(d, a.x, bb.x);
    r.y = fmaf(d, a.y, bb.y);
    r.z = fmaf(d, a.z, bb.z);
    r.w = fmaf(d, a.w, bb.w);
    reinterpret_cast<float4*>(out)[idx] = r;
}

// ---------------------------------------------------------------------------
extern "C" void kernel_launch(void* const* d_in, const int* in_sizes, int n_in,
                              void* d_out, int out_size)
{
    const float* x  = (const float*)d_in[0];       // [N, 256]
    const void*  ei = d_in[1];                     // [2, E] int32 (or int64)
    const float* W1 = (const float*)d_in[2];       // [256, 128]
    const float* b1 = (const float*)d_in[3];       // [128]
    const float* W2 = (const float*)d_in[4];       // [128, 128]
    const float* b2 = (const float*)d_in[5];       // [128]
    float*       out = (float*)d_out;              // [N, 128]

    const int M = in_sizes[0] / DIN;       // 50000
    const int E = in_sizes[1] / 2;         // 800000

    // 0. edge dtype probe (writes g_is64)
    k_detect<<<1, 1>>>((const int*)ei);

    // 1. degree / dis
    k_init_deg<<<(M + 255) / 256, 256>>>(M);
    k_count_deg<<<(E + 255) / 256, 256>>>(ei, E);
    k_rsqrt<<<(M + 255) / 256, 256>>>(M);

    const int gemm_grid = (M + 127) / 128;
    const int scat_grid = (int)(((long long)E * 32 + 255) / 256);
    const int fin_grid  = (M * 32 + 255) / 256;

    // 2. layer 1  (accumulate in g_acc)
    k_gemm_scale<DIN, false><<<gemm_grid, 256>>>(x, W1, M);
    k_scatter<<<scat_grid, 256>>>(ei, E);
    k_finalize_relu<<<fin_grid, 256>>>(b1, M);

    // 3. layer 2  (A = g_hs in-kernel; d_out via plain stores)
    k_gemm_scale<DH, true><<<gemm_grid, 256>>>(x, W2, M);
    k_scatter<<<scat_grid, 256>>>(ei, E);
    k_finalize<<<fin_grid, 256>>>(b2, out, M);
}

// round 9
// speedup vs baseline: 1.8480x; 1.8480x over previous
#include <cuda_runtime.h>
#include <cuda_bf16.h>
#include <stdint.h>

// Problem shape (fixed by the dataset)
#define NNODES   50000
#define DIN      256
#define DH       128

// Device scratch — referenced DIRECTLY from kernels.
__device__ __align__(16) float g_dis[NNODES];          // deg -> rsqrt(deg)
__device__ __align__(16) float g_hs [NNODES * DH];     // scaled h / x1 (aliased)
__device__ __align__(16) float g_acc[NNODES * DH];     // aggregation accumulator
__device__ int g_is64;                                  // edge dtype flag

// ---------------------------------------------------------------------------
// Edge-index dtype probe (robust to int32/int64 delivery)
// ---------------------------------------------------------------------------
__global__ void k_detect(const int* __restrict__ ei32) {
    int nz = 0;
#pragma unroll
    for (int i = 1; i < 64; i += 2) nz |= ei32[i];
    g_is64 = (nz == 0) ? 1 : 0;
}

__device__ __forceinline__ int load_idx(const void* ei, long long pos) {
    if (g_is64) return (int)((const long long*)ei)[pos];
    return ((const int*)ei)[pos];
}

// ---------------------------------------------------------------------------
// degree / normalization
// ---------------------------------------------------------------------------
__global__ void k_init_deg(int n) {
    int i = blockIdx.x * blockDim.x + threadIdx.x;
    if (i < n) g_dis[i] = 1.0f;  // self loop
}

__global__ void k_count_deg(const void* __restrict__ ei, int E) {
    int e = blockIdx.x * blockDim.x + threadIdx.x;
    if (e < E) {
        int d = load_idx(ei, (long long)E + e);
        atomicAdd(&g_dis[d], 1.0f);
    }
}

__global__ void k_rsqrt(int n) {
    int i = blockIdx.x * blockDim.x + threadIdx.x;
    if (i < n) g_dis[i] = rsqrtf(g_dis[i]);
}

// ---------------------------------------------------------------------------
// tf32 helpers: split fp32 into tf32 hi + tf32 lo (3-term MMA gives ~fp32)
// ---------------------------------------------------------------------------
__device__ __forceinline__ void f32_to_tf32x2(float a, uint32_t& hi, uint32_t& lo) {
    asm("cvt.rna.tf32.f32 %0, %1;" : "=r"(hi) : "f"(a));
    float l = a - __uint_as_float(hi);
    asm("cvt.rna.tf32.f32 %0, %1;" : "=r"(lo) : "f"(l));
}

__device__ __forceinline__ void mma_tf32(float* d, const uint32_t* a, const uint32_t* b) {
    asm volatile(
        "mma.sync.aligned.m16n8k8.row.col.f32.tf32.tf32.f32 "
        "{%0,%1,%2,%3}, {%4,%5,%6,%7}, {%8,%9}, {%0,%1,%2,%3};"
        : "+f"(d[0]), "+f"(d[1]), "+f"(d[2]), "+f"(d[3])
        : "r"(a[0]), "r"(a[1]), "r"(a[2]), "r"(a[3]), "r"(b[0]), "r"(b[1]));
}

// ---------------------------------------------------------------------------
// Tensor-core GEMM (tf32x3): C = A[M,K] @ W[K,128], epilogue scales rows by
// dis and writes to BOTH g_hs and g_acc. LAYER2 selects A = g_hs (in-place
// safe: each block reads only its own 128-row slice before overwriting it).
// BM=128, BN=128, BK=16; 8 warps as 4(M)x2(N); warp tile 32x64.
// ---------------------------------------------------------------------------
#define AS_STRIDE 20
#define BS_STRIDE 136

template <int K, bool LAYER2>
__global__ __launch_bounds__(256) void k_gemm_tf32(
    const float* __restrict__ Ain, const float* __restrict__ W, int M)
{
    const float* __restrict__ A = LAYER2 ? (const float*)g_hs : Ain;

    __shared__ __align__(16) float As[128 * AS_STRIDE];  // [m][k], pad->20
    __shared__ __align__(16) float Bs[16 * BS_STRIDE];   // [k][n], pad->136

    const int tid    = threadIdx.x;
    const int lane   = tid & 31;
    const int wid    = tid >> 5;
    const int warp_m = wid & 3;           // 0..3 -> rows warp_m*32
    const int warp_n = wid >> 2;          // 0..1 -> cols warp_n*64
    const int qrow   = lane >> 2;         // 0..7
    const int qcol   = lane & 3;          // 0..3
    const int block_row = blockIdx.x * 128;

    float acc[2][8][4];
#pragma unroll
    for (int mt = 0; mt < 2; mt++)
#pragma unroll
        for (int nt = 0; nt < 8; nt++)
#pragma unroll
            for (int r = 0; r < 4; r++) acc[mt][nt][r] = 0.0f;

    for (int k0 = 0; k0 < K; k0 += 16) {
        // Load A tile 128x16 (512 float4 -> 2 per thread), [m][k] layout
#pragma unroll
        for (int i = 0; i < 2; i++) {
            int lin = tid * 2 + i;           // 0..511
            int r   = lin >> 2;              // 0..127
            int c4  = lin & 3;               // float4 along k
            int gr  = block_row + r;
            float4 v = make_float4(0.f, 0.f, 0.f, 0.f);
            if (gr < M)
                v = reinterpret_cast<const float4*>(A + (size_t)gr * K + k0)[c4];
            reinterpret_cast<float4*>(As + r * AS_STRIDE + c4 * 4)[0] = v;
        }
        // Load W tile 16x128, [k][n] layout
#pragma unroll
        for (int i = 0; i < 2; i++) {
            int lin = tid * 2 + i;
            int kr  = lin >> 5;              // 0..15
            int c4  = lin & 31;
            float4 v = reinterpret_cast<const float4*>(W + (size_t)(k0 + kr) * 128)[c4];
            reinterpret_cast<float4*>(Bs + kr * BS_STRIDE + c4 * 4)[0] = v;
        }
        __syncthreads();

#pragma unroll
        for (int ks = 0; ks < 16; ks += 8) {
            // A fragments for 2 m-tiles, split hi/lo
            uint32_t ahi[2][4], alo[2][4];
#pragma unroll
            for (int mt = 0; mt < 2; mt++) {
                int r0 = warp_m * 32 + mt * 16 + qrow;
                float a0 = As[(r0    ) * AS_STRIDE + ks + qcol    ];
                float a1 = As[(r0 + 8) * AS_STRIDE + ks + qcol    ];
                float a2 = As[(r0    ) * AS_STRIDE + ks + qcol + 4];
                float a3 = As[(r0 + 8) * AS_STRIDE + ks + qcol + 4];
                f32_to_tf32x2(a0, ahi[mt][0], alo[mt][0]);
                f32_to_tf32x2(a1, ahi[mt][1], alo[mt][1]);
                f32_to_tf32x2(a2, ahi[mt][2], alo[mt][2]);
                f32_to_tf32x2(a3, ahi[mt][3], alo[mt][3]);
            }
#pragma unroll
            for (int nt = 0; nt < 8; nt++) {
                int n = warp_n * 64 + nt * 8 + qrow;
                float b0 = Bs[(ks + qcol    ) * BS_STRIDE + n];
                float b1 = Bs[(ks + qcol + 4) * BS_STRIDE + n];
                uint32_t bhi[2], blo[2];
                f32_to_tf32x2(b0, bhi[0], blo[0]);
                f32_to_tf32x2(b1, bhi[1], blo[1]);
#pragma unroll
                for (int mt = 0; mt < 2; mt++) {
                    mma_tf32(acc[mt][nt], ahi[mt], blo);
                    mma_tf32(acc[mt][nt], alo[mt], bhi);
                    mma_tf32(acc[mt][nt], ahi[mt], bhi);
                }
            }
        }
        __syncthreads();
    }

    // Epilogue: scale rows by dis, store float2 pairs to g_hs and g_acc
#pragma unroll
    for (int mt = 0; mt < 2; mt++) {
        int r0 = block_row + warp_m * 32 + mt * 16 + qrow;
        int r1 = r0 + 8;
        float d0 = (r0 < M) ? g_dis[r0] : 0.f;
        float d1 = (r1 < M) ? g_dis[r1] : 0.f;
#pragma unroll
        for (int nt = 0; nt < 8; nt++) {
            int c = warp_n * 64 + nt * 8 + 2 * qcol;
            if (r0 < M) {
                float2 v = make_float2(acc[mt][nt][0] * d0, acc[mt][nt][1] * d0);
                size_t off = (size_t)r0 * 128 + c;
                reinterpret_cast<float2*>(g_hs  + off)[0] = v;
                reinterpret_cast<float2*>(g_acc + off)[0] = v;
            }
            if (r1 < M) {
                float2 v = make_float2(acc[mt][nt][2] * d1, acc[mt][nt][3] * d1);
                size_t off = (size_t)r1 * 128 + c;
                reinterpret_cast<float2*>(g_hs  + off)[0] = v;
                reinterpret_cast<float2*>(g_acc + off)[0] = v;
            }
        }
    }
}

// ---------------------------------------------------------------------------
// Scatter: g_acc[dst] += g_hs[src]. One warp per edge; each lane does one
// 16B vector reduction (red.global.add.v4.f32, sm_90+, no return).
// ---------------------------------------------------------------------------
__global__ __launch_bounds__(256) void k_scatter(
    const void* __restrict__ ei, int E)
{
    int idx  = blockIdx.x * blockDim.x + threadIdx.x;
    int e    = idx >> 5;
    int lane = idx & 31;
    if (e >= E) return;
    int s = load_idx(ei, e);
    int d = load_idx(ei, (long long)E + e);
    float4 v = reinterpret_cast<const float4*>(g_hs + (size_t)s * 128)[lane];
    float* p = g_acc + (size_t)d * 128 + lane * 4;
    asm volatile("red.global.add.v4.f32 [%0], {%1,%2,%3,%4};"
                 :: "l"(p), "f"(v.x), "f"(v.y), "f"(v.z), "f"(v.w) : "memory");
}

// ---------------------------------------------------------------------------
// Finalize layer 1: g_hs = relu(dis[i] * g_acc + b1[j])
// ---------------------------------------------------------------------------
__global__ void k_finalize_relu(const float* __restrict__ b, int M)
{
    int idx = blockIdx.x * blockDim.x + threadIdx.x;   // float4 index
    if (idx >= M * 32) return;
    int i  = idx >> 5;
    int j4 = (idx & 31);
    float d = g_dis[i];
    float4 a = reinterpret_cast<const float4*>(g_acc)[idx];
    float4 bb = reinterpret_cast<const float4*>(b)[j4];
    float4 r;
    r.x = fmaxf(fmaf(d, a.x, bb.x), 0.f);
    r.y = fmaxf(fmaf(d, a.y, bb.y), 0.f);
    r.z = fmaxf(fmaf(d, a.z, bb.z), 0.f);
    r.w = fmaxf(fmaf(d, a.w, bb.w), 0.f);
    reinterpret_cast<float4*>(g_hs)[idx] = r;
}

// Finalize layer 2: out = dis[i]*g_acc + b2[j]  (plain stores into d_out only)
__global__ void k_finalize(const float* __restrict__ b,
                           float* __restrict__ out, int M)
{
    int idx = blockIdx.x * blockDim.x + threadIdx.x;
    if (idx >= M * 32) return;
    int i  = idx >> 5;
    int j4 = (idx & 31);
    float d = g_dis[i];
    float4 a = reinterpret_cast<const float4*>(g_acc)[idx];
    float4 bb = reinterpret_cast<const float4*>(b)[j4];
    float4 r;
    r.x = fmaf(d, a.x, bb.x);
    r.y = fmaf(d, a.y, bb.y);
    r.z = fmaf(d, a.z, bb.z);
    r.w = fmaf(d, a.w, bb.w);
    reinterpret_cast<float4*>(out)[idx] = r;
}

// ---------------------------------------------------------------------------
extern "C" void kernel_launch(void* const* d_in, const int* in_sizes, int n_in,
                              void* d_out, int out_size)
{
    const float* x  = (const float*)d_in[0];       // [N, 256]
    const void*  ei = d_in[1];                     // [2, E] int32 (or int64)
    const float* W1 = (const float*)d_in[2];       // [256, 128]
    const float* b1 = (const float*)d_in[3];       // [128]
    const float* W2 = (const float*)d_in[4];       // [128, 128]
    const float* b2 = (const float*)d_in[5];       // [128]
    float*       out = (float*)d_out;              // [N, 128]

    const int M = in_sizes[0] / DIN;       // 50000
    const int E = in_sizes[1] / 2;         // 800000

    // 0. edge dtype probe
    k_detect<<<1, 1>>>((const int*)ei);

    // 1. degree / dis
    k_init_deg<<<(M + 255) / 256, 256>>>(M);
    k_count_deg<<<(E + 255) / 256, 256>>>(ei, E);
    k_rsqrt<<<(M + 255) / 256, 256>>>(M);

    const int gemm_grid = (M + 127) / 128;
    const int scat_grid = (int)(((long long)E * 32 + 255) / 256);
    const int fin_grid  = (M * 32 + 255) / 256;

    // 2. layer 1  (accumulate in g_acc)
    k_gemm_tf32<DIN, false><<<gemm_grid, 256>>>(x, W1, M);
    k_scatter<<<scat_grid, 256>>>(ei, E);
    k_finalize_relu<<<fin_grid, 256>>>(b1, M);

    // 3. layer 2  (A = g_hs in-kernel; d_out via plain stores)
    k_gemm_tf32<DH, true><<<gemm_grid, 256>>>(x, W2, M);
    k_scatter<<<scat_grid, 256>>>(ei, E);
    k_finalize<<<fin_grid, 256>>>(b2, out, M);
}

// round 11
// speedup vs baseline: 2.8679x; 1.5519x over previous
#include <cuda_runtime.h>
#include <cuda_bf16.h>
#include <stdint.h>

// Problem shape (fixed by the dataset)
#define NNODES   50000
#define DIN      256
#define DH       128
#define NBLK     ((NNODES + 255) / 256)     // 196

// Device scratch — referenced DIRECTLY from kernels (device code ONLY;
// host-side references to __device__ symbols yield shadow addresses).
__device__ __align__(16) float g_dis[NNODES];           // rsqrt(1+deg)
__device__ __align__(16) float g_hs [NNODES * DH];      // dis[i]*(A@W) rows
__device__ __align__(16) float g_x1 [NNODES * DH];      // layer-1 output
__device__ int g_cnt[NNODES];                            // in-degree counts
__device__ int g_rowptr[NNODES + 1];                     // CSR row pointers
__device__ int g_cursor[NNODES];                         // fill cursors
__device__ int g_csr[800000 + 1024];                     // CSR src lists
__device__ int g_bsum[NBLK];                             // per-block count sums
__device__ int g_boff[NBLK];                             // scanned block offsets
__device__ int g_is64;                                   // edge dtype flag

// ---------------------------------------------------------------------------
// Edge-index dtype probe (robust to int32/int64 delivery)
// ---------------------------------------------------------------------------
__global__ void k_detect(const int* __restrict__ ei32) {
    int nz = 0;
#pragma unroll
    for (int i = 1; i < 64; i += 2) nz |= ei32[i];
    g_is64 = (nz == 0) ? 1 : 0;
}

__device__ __forceinline__ int load_idx(const void* ei, long long pos) {
    if (g_is64) return (int)((const long long*)ei)[pos];
    return ((const int*)ei)[pos];
}

// ---------------------------------------------------------------------------
// CSR build: zero -> count -> blocksum(+dis) -> scan -> rowptr -> fill
// ---------------------------------------------------------------------------
__global__ void k_zero(int n) {
    int i = blockIdx.x * blockDim.x + threadIdx.x;
    if (i < n) g_cnt[i] = 0;
}

__global__ void k_count(const void* __restrict__ ei, int E) {
    int e = blockIdx.x * blockDim.x + threadIdx.x;
    if (e < E) atomicAdd(&g_cnt[load_idx(ei, (long long)E + e)], 1);
}

__global__ void k_blocksum(int n) {      // grid NBLK, block 256
    __shared__ int sh[256];
    int t = threadIdx.x;
    int i = blockIdx.x * 256 + t;
    int c = (i < n) ? g_cnt[i] : 0;
    if (i < n) g_dis[i] = rsqrtf((float)(1 + c));   // self loop included
    sh[t] = c; __syncthreads();
#pragma unroll
    for (int off = 128; off > 0; off >>= 1) {
        if (t < off) sh[t] += sh[t + off];
        __syncthreads();
    }
    if (t == 0) g_bsum[blockIdx.x] = sh[0];
}

__global__ void k_scanbsum() {           // 1 block, 256 threads
    __shared__ int sh[256];
    int t = threadIdx.x;
    int v = (t < NBLK) ? g_bsum[t] : 0;
    sh[t] = v; __syncthreads();
#pragma unroll
    for (int off = 1; off < 256; off <<= 1) {
        int u = (t >= off) ? sh[t - off] : 0;
        __syncthreads();
        sh[t] += u;
        __syncthreads();
    }
    if (t < NBLK) g_boff[t] = sh[t] - v;   // exclusive
}

__global__ void k_rowptr(int n, int E) { // grid NBLK, block 256
    __shared__ int sh[256];
    int t = threadIdx.x;
    int i = blockIdx.x * 256 + t;
    int c = (i < n) ? g_cnt[i] : 0;
    sh[t] = c; __syncthreads();
#pragma unroll
    for (int off = 1; off < 256; off <<= 1) {
        int u = (t >= off) ? sh[t - off] : 0;
        __syncthreads();
        sh[t] += u;
        __syncthreads();
    }
    if (i < n) {
        int val = g_boff[blockIdx.x] + sh[t] - c;   // exclusive
        g_rowptr[i] = val;
        g_cursor[i] = val;
        if (i == n - 1) g_rowptr[n] = E;
    }
}

__global__ void k_fill(const void* __restrict__ ei, int E) {
    int e = blockIdx.x * blockDim.x + threadIdx.x;
    if (e >= E) return;
    int s = load_idx(ei, e);
    int d = load_idx(ei, (long long)E + e);
    int pos = atomicAdd(&g_cursor[d], 1);
    g_csr[pos] = s;
}

// ---------------------------------------------------------------------------
// tf32 helpers: split fp32 into tf32 hi + tf32 lo (3-term MMA gives ~fp32)
// ---------------------------------------------------------------------------
__device__ __forceinline__ void f32_to_tf32x2(float a, uint32_t& hi, uint32_t& lo) {
    asm("cvt.rna.tf32.f32 %0, %1;" : "=r"(hi) : "f"(a));
    float l = a - __uint_as_float(hi);
    asm("cvt.rna.tf32.f32 %0, %1;" : "=r"(lo) : "f"(l));
}

__device__ __forceinline__ void mma_tf32(float* d, const uint32_t* a, const uint32_t* b) {
    asm volatile(
        "mma.sync.aligned.m16n8k8.row.col.f32.tf32.tf32.f32 "
        "{%0,%1,%2,%3}, {%4,%5,%6,%7}, {%8,%9}, {%0,%1,%2,%3};"
        : "+f"(d[0]), "+f"(d[1]), "+f"(d[2]), "+f"(d[3])
        : "r"(a[0]), "r"(a[1]), "r"(a[2]), "r"(a[3]), "r"(b[0]), "r"(b[1]));
}

// ---------------------------------------------------------------------------
// Tensor-core GEMM (tf32x3): g_hs = dis[i] * (A[M,K] @ W[K,128]).
// LAYER2 selects A = g_x1 (device-side symbol use). 8 warps 4(M)x2(N).
// ---------------------------------------------------------------------------
#define AS_STRIDE 20
#define BS_STRIDE 136

template <int K, bool LAYER2>
__global__ __launch_bounds__(256) void k_gemm_tf32(
    const float* __restrict__ Ain, const float* __restrict__ W, int M)
{
    const float* __restrict__ A = LAYER2 ? (const float*)g_x1 : Ain;

    __shared__ __align__(16) float As[128 * AS_STRIDE];
    __shared__ __align__(16) float Bs[16 * BS_STRIDE];

    const int tid    = threadIdx.x;
    const int lane   = tid & 31;
    const int wid    = tid >> 5;
    const int warp_m = wid & 3;
    const int warp_n = wid >> 2;
    const int qrow   = lane >> 2;
    const int qcol   = lane & 3;
    const int block_row = blockIdx.x * 128;

    float acc[2][8][4];
#pragma unroll
    for (int mt = 0; mt < 2; mt++)
#pragma unroll
        for (int nt = 0; nt < 8; nt++)
#pragma unroll
            for (int r = 0; r < 4; r++) acc[mt][nt][r] = 0.0f;

    for (int k0 = 0; k0 < K; k0 += 16) {
#pragma unroll
        for (int i = 0; i < 2; i++) {
            int lin = tid * 2 + i;
            int r   = lin >> 2;
            int c4  = lin & 3;
            int gr  = block_row + r;
            float4 v = make_float4(0.f, 0.f, 0.f, 0.f);
            if (gr < M)
                v = reinterpret_cast<const float4*>(A + (size_t)gr * K + k0)[c4];
            reinterpret_cast<float4*>(As + r * AS_STRIDE + c4 * 4)[0] = v;
        }
#pragma unroll
        for (int i = 0; i < 2; i++) {
            int lin = tid * 2 + i;
            int kr  = lin >> 5;
            int c4  = lin & 31;
            float4 v = reinterpret_cast<const float4*>(W + (size_t)(k0 + kr) * 128)[c4];
            reinterpret_cast<float4*>(Bs + kr * BS_STRIDE + c4 * 4)[0] = v;
        }
        __syncthreads();

#pragma unroll
        for (int ks = 0; ks < 16; ks += 8) {
            uint32_t ahi[2][4], alo[2][4];
#pragma unroll
            for (int mt = 0; mt < 2; mt++) {
                int r0 = warp_m * 32 + mt * 16 + qrow;
                float a0 = As[(r0    ) * AS_STRIDE + ks + qcol    ];
                float a1 = As[(r0 + 8) * AS_STRIDE + ks + qcol    ];
                float a2 = As[(r0    ) * AS_STRIDE + ks + qcol + 4];
                float a3 = As[(r0 + 8) * AS_STRIDE + ks + qcol + 4];
                f32_to_tf32x2(a0, ahi[mt][0], alo[mt][0]);
                f32_to_tf32x2(a1, ahi[mt][1], alo[mt][1]);
                f32_to_tf32x2(a2, ahi[mt][2], alo[mt][2]);
                f32_to_tf32x2(a3, ahi[mt][3], alo[mt][3]);
            }
#pragma unroll
            for (int nt = 0; nt < 8; nt++) {
                int n = warp_n * 64 + nt * 8 + qrow;
                float b0 = Bs[(ks + qcol    ) * BS_STRIDE + n];
                float b1 = Bs[(ks + qcol + 4) * BS_STRIDE + n];
                uint32_t bhi[2], blo[2];
                f32_to_tf32x2(b0, bhi[0], blo[0]);
                f32_to_tf32x2(b1, bhi[1], blo[1]);
#pragma unroll
                for (int mt = 0; mt < 2; mt++) {
                    mma_tf32(acc[mt][nt], ahi[mt], blo);
                    mma_tf32(acc[mt][nt], alo[mt], bhi);
                    mma_tf32(acc[mt][nt], ahi[mt], bhi);
                }
            }
        }
        __syncthreads();
    }

    // Epilogue: scale rows by dis, store to g_hs only
#pragma unroll
    for (int mt = 0; mt < 2; mt++) {
        int r0 = block_row + warp_m * 32 + mt * 16 + qrow;
        int r1 = r0 + 8;
        float d0 = (r0 < M) ? g_dis[r0] : 0.f;
        float d1 = (r1 < M) ? g_dis[r1] : 0.f;
#pragma unroll
        for (int nt = 0; nt < 8; nt++) {
            int c = warp_n * 64 + nt * 8 + 2 * qcol;
            if (r0 < M) {
                float2 v = make_float2(acc[mt][nt][0] * d0, acc[mt][nt][1] * d0);
                reinterpret_cast<float2*>(g_hs + (size_t)r0 * 128 + c)[0] = v;
            }
            if (r1 < M) {
                float2 v = make_float2(acc[mt][nt][2] * d1, acc[mt][nt][3] * d1);
                reinterpret_cast<float2*>(g_hs + (size_t)r1 * 128 + c)[0] = v;
            }
        }
    }
}

// ---------------------------------------------------------------------------
// CSR gather + fused finalize: one warp per node.
//   row = dis[i] * ( hs[i] + sum_{e: dst=i} hs[src_e] ) + b    (+relu)
// WRITE_X1 selects the g_x1 device symbol as destination IN DEVICE CODE
// (host-side &g_x1 would be a shadow address — the R10 bug).
// ---------------------------------------------------------------------------
template <bool RELU, bool WRITE_X1>
__global__ __launch_bounds__(256) void k_gather(
    const float* __restrict__ b, float* __restrict__ out_arg, int M)
{
    float* __restrict__ out = WRITE_X1 ? (float*)g_x1 : out_arg;

    int w    = (blockIdx.x * 256 + threadIdx.x) >> 5;
    int lane = threadIdx.x & 31;
    if (w >= M) return;

    int start = g_rowptr[w];
    int end   = g_rowptr[w + 1];

    // self-loop contribution
    float4 acc = reinterpret_cast<const float4*>(g_hs + (size_t)w * 128)[lane];

    for (int chunk = start; chunk < end; chunk += 32) {
        int remaining = end - chunk;
        int cnt   = remaining < 32 ? remaining : 32;
        int myidx = (lane < cnt) ? g_csr[chunk + lane] : 0;
#pragma unroll 4
        for (int j = 0; j < cnt; j++) {
            int s = __shfl_sync(0xffffffffu, myidx, j);
            float4 v = reinterpret_cast<const float4*>(g_hs + (size_t)s * 128)[lane];
            acc.x += v.x; acc.y += v.y; acc.z += v.z; acc.w += v.w;
        }
    }

    float d = g_dis[w];
    float4 bb = reinterpret_cast<const float4*>(b)[lane];
    float4 r;
    r.x = fmaf(d, acc.x, bb.x);
    r.y = fmaf(d, acc.y, bb.y);
    r.z = fmaf(d, acc.z, bb.z);
    r.w = fmaf(d, acc.w, bb.w);
    if (RELU) {
        r.x = fmaxf(r.x, 0.f); r.y = fmaxf(r.y, 0.f);
        r.z = fmaxf(r.z, 0.f); r.w = fmaxf(r.w, 0.f);
    }
    reinterpret_cast<float4*>(out + (size_t)w * 128)[lane] = r;
}

// ---------------------------------------------------------------------------
extern "C" void kernel_launch(void* const* d_in, const int* in_sizes, int n_in,
                              void* d_out, int out_size)
{
    const float* x  = (const float*)d_in[0];       // [N, 256]
    const void*  ei = d_in[1];                     // [2, E] int32 (or int64)
    const float* W1 = (const float*)d_in[2];       // [256, 128]
    const float* b1 = (const float*)d_in[3];       // [128]
    const float* W2 = (const float*)d_in[4];       // [128, 128]
    const float* b2 = (const float*)d_in[5];       // [128]
    float*       out = (float*)d_out;              // [N, 128]

    const int M = in_sizes[0] / DIN;       // 50000
    const int E = in_sizes[1] / 2;         // 800000

    const int nblk   = (M + 255) / 256;
    const int eblk   = (E + 255) / 256;
    const int gemm_g = (M + 127) / 128;
    const int gath_g = (M * 32 + 255) / 256;   // 8 warps/block, 1 node/warp

    // 0. dtype probe + CSR build (+ dis)
    k_detect<<<1, 1>>>((const int*)ei);
    k_zero<<<nblk, 256>>>(M);
    k_count<<<eblk, 256>>>(ei, E);
    k_blocksum<<<nblk, 256>>>(M);
    k_scanbsum<<<1, 256>>>();
    k_rowptr<<<nblk, 256>>>(M, E);
    k_fill<<<eblk, 256>>>(ei, E);

    // 1. layer 1: hs = dis*(x@W1); x1 = relu(dis*(hs_self + gather) + b1)
    k_gemm_tf32<DIN, false><<<gemm_g, 256>>>(x, W1, M);
    k_gather<true, true><<<gath_g, 256>>>(b1, nullptr, M);

    // 2. layer 2: hs = dis*(x1@W2); out = dis*(hs_self + gather) + b2
    k_gemm_tf32<DH, true><<<gemm_g, 256>>>(x, W2, M);
    k_gather<false, false><<<gath_g, 256>>>(b2, out, M);
}

// round 12
// speedup vs baseline: 3.4408x; 1.1997x over previous
#include <cuda_runtime.h>
#include <cuda_bf16.h>
#include <stdint.h>

// Problem shape (fixed by the dataset)
#define NNODES   50000
#define DIN      256
#define DH       128
#define NBLK     ((NNODES + 255) / 256)     // 196

// Device scratch — referenced DIRECTLY from kernels (device code ONLY).
__device__ __align__(16) float g_dis[NNODES];           // rsqrt(1+deg)
__device__ __align__(16) float g_hs [NNODES * DH];      // dis[i]*(A@W) rows
__device__ __align__(16) float g_x1 [NNODES * DH];      // layer-1 output
__device__ int g_cnt[NNODES];
__device__ int g_rowptr[NNODES + 1];
__device__ int g_cursor[NNODES];
__device__ int g_csr[800000 + 1024];
__device__ int g_bsum[NBLK];
__device__ int g_boff[NBLK];
__device__ int g_is64;
// Pre-converted weights: bf16x2-packed hi/lo, TRANSPOSED to [n][k/2] words.
__device__ __align__(16) uint32_t g_w1h[128 * 128];     // W1: n=128, k/2=128
__device__ __align__(16) uint32_t g_w1l[128 * 128];
__device__ __align__(16) uint32_t g_w2h[128 * 64];      // W2: n=128, k/2=64
__device__ __align__(16) uint32_t g_w2l[128 * 64];

// ---------------------------------------------------------------------------
// Edge-index dtype probe (robust to int32/int64 delivery)
// ---------------------------------------------------------------------------
__global__ void k_detect(const int* __restrict__ ei32) {
    int nz = 0;
#pragma unroll
    for (int i = 1; i < 64; i += 2) nz |= ei32[i];
    g_is64 = (nz == 0) ? 1 : 0;
}

__device__ __forceinline__ int load_idx(const void* ei, long long pos) {
    if (g_is64) return (int)((const long long*)ei)[pos];
    return ((const int*)ei)[pos];
}

// ---------------------------------------------------------------------------
// CSR build: zero -> count -> blocksum(+dis) -> scan -> rowptr -> fill
// ---------------------------------------------------------------------------
__global__ void k_zero(int n) {
    int i = blockIdx.x * blockDim.x + threadIdx.x;
    if (i < n) g_cnt[i] = 0;
}

__global__ void k_count(const void* __restrict__ ei, int E) {
    int e = blockIdx.x * blockDim.x + threadIdx.x;
    if (e < E) atomicAdd(&g_cnt[load_idx(ei, (long long)E + e)], 1);
}

__global__ void k_blocksum(int n) {
    __shared__ int sh[256];
    int t = threadIdx.x;
    int i = blockIdx.x * 256 + t;
    int c = (i < n) ? g_cnt[i] : 0;
    if (i < n) g_dis[i] = rsqrtf((float)(1 + c));
    sh[t] = c; __syncthreads();
#pragma unroll
    for (int off = 128; off > 0; off >>= 1) {
        if (t < off) sh[t] += sh[t + off];
        __syncthreads();
    }
    if (t == 0) g_bsum[blockIdx.x] = sh[0];
}

__global__ void k_scanbsum() {
    __shared__ int sh[256];
    int t = threadIdx.x;
    int v = (t < NBLK) ? g_bsum[t] : 0;
    sh[t] = v; __syncthreads();
#pragma unroll
    for (int off = 1; off < 256; off <<= 1) {
        int u = (t >= off) ? sh[t - off] : 0;
        __syncthreads();
        sh[t] += u;
        __syncthreads();
    }
    if (t < NBLK) g_boff[t] = sh[t] - v;
}

__global__ void k_rowptr(int n, int E) {
    __shared__ int sh[256];
    int t = threadIdx.x;
    int i = blockIdx.x * 256 + t;
    int c = (i < n) ? g_cnt[i] : 0;
    sh[t] = c; __syncthreads();
#pragma unroll
    for (int off = 1; off < 256; off <<= 1) {
        int u = (t >= off) ? sh[t - off] : 0;
        __syncthreads();
        sh[t] += u;
        __syncthreads();
    }
    if (i < n) {
        int val = g_boff[blockIdx.x] + sh[t] - c;
        g_rowptr[i] = val;
        g_cursor[i] = val;
        if (i == n - 1) g_rowptr[n] = E;
    }
}

__global__ void k_fill(const void* __restrict__ ei, int E) {
    int e = blockIdx.x * blockDim.x + threadIdx.x;
    if (e >= E) return;
    int s = load_idx(ei, e);
    int d = load_idx(ei, (long long)E + e);
    int pos = atomicAdd(&g_cursor[d], 1);
    g_csr[pos] = s;
}

// ---------------------------------------------------------------------------
// bf16 split helpers: pack (x,y) -> bf16x2 hi word + residual lo word.
// bf16->f32 is exact via bits<<16, so residual extraction is 2 shifts + 2 subs.
// ---------------------------------------------------------------------------
__device__ __forceinline__ void bf16_split2(float x, float y,
                                            uint32_t& hw, uint32_t& lw) {
    asm("cvt.rn.bf16x2.f32 %0, %1, %2;" : "=r"(hw) : "f"(y), "f"(x));
    float fx = __uint_as_float(hw << 16);
    float fy = __uint_as_float(hw & 0xffff0000u);
    asm("cvt.rn.bf16x2.f32 %0, %1, %2;" : "=r"(lw) : "f"(y - fy), "f"(x - fx));
}

__device__ __forceinline__ void mma_bf16(float* d, const uint32_t* a,
                                         const uint32_t* b) {
    asm volatile(
        "mma.sync.aligned.m16n8k16.row.col.f32.bf16.bf16.f32 "
        "{%0,%1,%2,%3}, {%4,%5,%6,%7}, {%8,%9}, {%0,%1,%2,%3};"
        : "+f"(d[0]), "+f"(d[1]), "+f"(d[2]), "+f"(d[3])
        : "r"(a[0]), "r"(a[1]), "r"(a[2]), "r"(a[3]), "r"(b[0]), "r"(b[1]));
}

// ---------------------------------------------------------------------------
// Weight pre-convert: W[K][128] fp32 -> transposed packed [n][k/2] hi/lo.
// ---------------------------------------------------------------------------
template <bool L2>
__global__ void k_wconv(const float* __restrict__ W) {
    constexpr int K  = L2 ? DH : DIN;
    constexpr int KW = K / 2;
    uint32_t* H = L2 ? g_w2h : g_w1h;
    uint32_t* L = L2 ? g_w2l : g_w1l;
    int idx = blockIdx.x * blockDim.x + threadIdx.x;
    if (idx >= 128 * KW) return;
    int kp = idx % KW;
    int n  = idx / KW;
    float x = W[(2 * kp    ) * 128 + n];
    float y = W[(2 * kp + 1) * 128 + n];
    uint32_t hw, lw;
    bf16_split2(x, y, hw, lw);
    H[idx] = hw;
    L[idx] = lw;
}

// ---------------------------------------------------------------------------
// Tensor-core GEMM (bf16 hi/lo x3, m16n8k16): g_hs = dis[i]*(A[M,K]@W[K,128]).
// A converted once at SMEM-store; W pre-converted globally. 8 warps 4(M)x2(N).
// SMEM word stride 12 => conflict-free fragment LDS for (qrow,qcol) pattern.
// ---------------------------------------------------------------------------
#define AS_STRIDE 12
#define BS_STRIDE 12

template <int K, bool LAYER2>
__global__ __launch_bounds__(256) void k_gemm_bf16(
    const float* __restrict__ Ain, int M)
{
    const float* __restrict__ A = LAYER2 ? (const float*)g_x1 : Ain;
    const uint32_t* __restrict__ WH = LAYER2 ? g_w2h : g_w1h;
    const uint32_t* __restrict__ WL = LAYER2 ? g_w2l : g_w1l;
    constexpr int KW = K / 2;

    __shared__ uint32_t Ash[128 * AS_STRIDE];
    __shared__ uint32_t Asl[128 * AS_STRIDE];
    __shared__ uint32_t Bsh[128 * BS_STRIDE];
    __shared__ uint32_t Bsl[128 * BS_STRIDE];

    const int tid    = threadIdx.x;
    const int lane   = tid & 31;
    const int wid    = tid >> 5;
    const int warp_m = wid & 3;
    const int warp_n = wid >> 2;
    const int qrow   = lane >> 2;
    const int qcol   = lane & 3;
    const int block_row = blockIdx.x * 128;

    // B tile load mapping: 128 n-rows x 8 words; one uint4 per thread.
    const int bn = tid >> 1;
    const int bw = (tid & 1) * 4;

    float acc[2][8][4];
#pragma unroll
    for (int mt = 0; mt < 2; mt++)
#pragma unroll
        for (int nt = 0; nt < 8; nt++)
#pragma unroll
            for (int r = 0; r < 4; r++) acc[mt][nt][r] = 0.0f;

    for (int k0 = 0; k0 < K; k0 += 16) {
        // A tile 128x16: 2 float4 per thread, convert+split at store
#pragma unroll
        for (int i = 0; i < 2; i++) {
            int lin = tid * 2 + i;
            int r   = lin >> 2;
            int c4  = lin & 3;
            int gr  = block_row + r;
            float4 v = make_float4(0.f, 0.f, 0.f, 0.f);
            if (gr < M)
                v = reinterpret_cast<const float4*>(A + (size_t)gr * K + k0)[c4];
            uint32_t h0, l0, h1, l1;
            bf16_split2(v.x, v.y, h0, l0);
            bf16_split2(v.z, v.w, h1, l1);
            Ash[r * AS_STRIDE + 2 * c4    ] = h0;
            Ash[r * AS_STRIDE + 2 * c4 + 1] = h1;
            Asl[r * AS_STRIDE + 2 * c4    ] = l0;
            Asl[r * AS_STRIDE + 2 * c4 + 1] = l1;
        }
        // B tile: pre-converted [n][k/2], coalesced uint4 loads
        {
            uint4 vh = reinterpret_cast<const uint4*>(WH + (size_t)bn * KW + k0 / 2)[bw >> 2];
            uint4 vl = reinterpret_cast<const uint4*>(WL + (size_t)bn * KW + k0 / 2)[bw >> 2];
            Bsh[bn * BS_STRIDE + bw + 0] = vh.x;
            Bsh[bn * BS_STRIDE + bw + 1] = vh.y;
            Bsh[bn * BS_STRIDE + bw + 2] = vh.z;
            Bsh[bn * BS_STRIDE + bw + 3] = vh.w;
            Bsl[bn * BS_STRIDE + bw + 0] = vl.x;
            Bsl[bn * BS_STRIDE + bw + 1] = vl.y;
            Bsl[bn * BS_STRIDE + bw + 2] = vl.z;
            Bsl[bn * BS_STRIDE + bw + 3] = vl.w;
        }
        __syncthreads();

        uint32_t ah[2][4], al[2][4];
#pragma unroll
        for (int mt = 0; mt < 2; mt++) {
            int r0 = warp_m * 32 + mt * 16 + qrow;
            ah[mt][0] = Ash[(r0    ) * AS_STRIDE + qcol    ];
            ah[mt][1] = Ash[(r0 + 8) * AS_STRIDE + qcol    ];
            ah[mt][2] = Ash[(r0    ) * AS_STRIDE + qcol + 4];
            ah[mt][3] = Ash[(r0 + 8) * AS_STRIDE + qcol + 4];
            al[mt][0] = Asl[(r0    ) * AS_STRIDE + qcol    ];
            al[mt][1] = Asl[(r0 + 8) * AS_STRIDE + qcol    ];
            al[mt][2] = Asl[(r0    ) * AS_STRIDE + qcol + 4];
            al[mt][3] = Asl[(r0 + 8) * AS_STRIDE + qcol + 4];
        }
#pragma unroll
        for (int nt = 0; nt < 8; nt++) {
            int n = warp_n * 64 + nt * 8 + qrow;
            uint32_t bh[2], bl[2];
            bh[0] = Bsh[n * BS_STRIDE + qcol    ];
            bh[1] = Bsh[n * BS_STRIDE + qcol + 4];
            bl[0] = Bsl[n * BS_STRIDE + qcol    ];
            bl[1] = Bsl[n * BS_STRIDE + qcol + 4];
#pragma unroll
            for (int mt = 0; mt < 2; mt++) {
                mma_bf16(acc[mt][nt], ah[mt], bl);
                mma_bf16(acc[mt][nt], al[mt], bh);
                mma_bf16(acc[mt][nt], ah[mt], bh);
            }
        }
        __syncthreads();
    }

    // Epilogue: scale rows by dis, store to g_hs
#pragma unroll
    for (int mt = 0; mt < 2; mt++) {
        int r0 = block_row + warp_m * 32 + mt * 16 + qrow;
        int r1 = r0 + 8;
        float d0 = (r0 < M) ? g_dis[r0] : 0.f;
        float d1 = (r1 < M) ? g_dis[r1] : 0.f;
#pragma unroll
        for (int nt = 0; nt < 8; nt++) {
            int c = warp_n * 64 + nt * 8 + 2 * qcol;
            if (r0 < M) {
                float2 v = make_float2(acc[mt][nt][0] * d0, acc[mt][nt][1] * d0);
                reinterpret_cast<float2*>(g_hs + (size_t)r0 * 128 + c)[0] = v;
            }
            if (r1 < M) {
                float2 v = make_float2(acc[mt][nt][2] * d1, acc[mt][nt][3] * d1);
                reinterpret_cast<float2*>(g_hs + (size_t)r1 * 128 + c)[0] = v;
            }
        }
    }
}

// ---------------------------------------------------------------------------
// CSR gather + fused finalize: one warp per node.
// ---------------------------------------------------------------------------
template <bool RELU, bool WRITE_X1>
__global__ __launch_bounds__(256) void k_gather(
    const float* __restrict__ b, float* __restrict__ out_arg, int M)
{
    float* __restrict__ out = WRITE_X1 ? (float*)g_x1 : out_arg;

    int w    = (blockIdx.x * 256 + threadIdx.x) >> 5;
    int lane = threadIdx.x & 31;
    if (w >= M) return;

    int start = g_rowptr[w];
    int end   = g_rowptr[w + 1];

    float4 acc = reinterpret_cast<const float4*>(g_hs + (size_t)w * 128)[lane];

    for (int chunk = start; chunk < end; chunk += 32) {
        int remaining = end - chunk;
        int cnt   = remaining < 32 ? remaining : 32;
        int myidx = (lane < cnt) ? g_csr[chunk + lane] : 0;
#pragma unroll 4
        for (int j = 0; j < cnt; j++) {
            int s = __shfl_sync(0xffffffffu, myidx, j);
            float4 v = reinterpret_cast<const float4*>(g_hs + (size_t)s * 128)[lane];
            acc.x += v.x; acc.y += v.y; acc.z += v.z; acc.w += v.w;
        }
    }

    float d = g_dis[w];
    float4 bb = reinterpret_cast<const float4*>(b)[lane];
    float4 r;
    r.x = fmaf(d, acc.x, bb.x);
    r.y = fmaf(d, acc.y, bb.y);
    r.z = fmaf(d, acc.z, bb.z);
    r.w = fmaf(d, acc.w, bb.w);
    if (RELU) {
        r.x = fmaxf(r.x, 0.f); r.y = fmaxf(r.y, 0.f);
        r.z = fmaxf(r.z, 0.f); r.w = fmaxf(r.w, 0.f);
    }
    reinterpret_cast<float4*>(out + (size_t)w * 128)[lane] = r;
}

// ---------------------------------------------------------------------------
extern "C" void kernel_launch(void* const* d_in, const int* in_sizes, int n_in,
                              void* d_out, int out_size)
{
    const float* x  = (const float*)d_in[0];       // [N, 256]
    const void*  ei = d_in[1];                     // [2, E] int32 (or int64)
    const float* W1 = (const float*)d_in[2];       // [256, 128]
    const float* b1 = (const float*)d_in[3];       // [128]
    const float* W2 = (const float*)d_in[4];       // [128, 128]
    const float* b2 = (const float*)d_in[5];       // [128]
    float*       out = (float*)d_out;              // [N, 128]

    const int M = in_sizes[0] / DIN;       // 50000
    const int E = in_sizes[1] / 2;         // 800000

    const int nblk   = (M + 255) / 256;
    const int eblk   = (E + 255) / 256;
    const int gemm_g = (M + 127) / 128;
    const int gath_g = (M * 32 + 255) / 256;

    // 0. dtype probe + weight pre-convert + CSR build (+ dis)
    k_detect<<<1, 1>>>((const int*)ei);
    k_wconv<false><<<(128 * 128 + 255) / 256, 256>>>(W1);
    k_wconv<true ><<<(128 * 64  + 255) / 256, 256>>>(W2);
    k_zero<<<nblk, 256>>>(M);
    k_count<<<eblk, 256>>>(ei, E);
    k_blocksum<<<nblk, 256>>>(M);
    k_scanbsum<<<1, 256>>>();
    k_rowptr<<<nblk, 256>>>(M, E);
    k_fill<<<eblk, 256>>>(ei, E);

    // 1. layer 1
    k_gemm_bf16<DIN, false><<<gemm_g, 256>>>(x, M);
    k_gather<true, true><<<gath_g, 256>>>(b1, nullptr, M);

    // 2. layer 2
    k_gemm_bf16<DH, true><<<gemm_g, 256>>>(x, M);
    k_gather<false, false><<<gath_g, 256>>>(b2, out, M);
}

// round 13
// speedup vs baseline: 3.5883x; 1.0429x over previous
#include <cuda_runtime.h>
#include <cuda_bf16.h>
#include <stdint.h>

// Problem shape (fixed by the dataset)
#define NNODES   50000
#define DIN      256
#define DH       128
#define NBLK     ((NNODES + 255) / 256)     // 196

// Device scratch — referenced DIRECTLY from kernels (device code ONLY).
__device__ __align__(16) float g_dis[NNODES];           // rsqrt(1+deg)
__device__ __align__(16) float g_hs [NNODES * DH];      // dis[i]*(A@W) rows
__device__ __align__(16) float g_x1 [NNODES * DH];      // layer-1 output
__device__ int g_cnt[NNODES];
__device__ int g_rowptr[NNODES + 1];
__device__ int g_cursor[NNODES];
__device__ int g_csr[800000 + 1024];
__device__ int g_bsum[NBLK];
__device__ int g_boff[NBLK];
__device__ int g_is64;
// Pre-converted weights: bf16x2-packed hi/lo, TRANSPOSED to [n][k/2] words.
__device__ __align__(16) uint32_t g_w1h[128 * 128];     // W1: n=128, k/2=128
__device__ __align__(16) uint32_t g_w1l[128 * 128];
__device__ __align__(16) uint32_t g_w2h[128 * 64];      // W2: n=128, k/2=64
__device__ __align__(16) uint32_t g_w2l[128 * 64];

// ---------------------------------------------------------------------------
// bf16 split helpers
// ---------------------------------------------------------------------------
__device__ __forceinline__ void bf16_split2(float x, float y,
                                            uint32_t& hw, uint32_t& lw) {
    asm("cvt.rn.bf16x2.f32 %0, %1, %2;" : "=r"(hw) : "f"(y), "f"(x));
    float fx = __uint_as_float(hw << 16);
    float fy = __uint_as_float(hw & 0xffff0000u);
    asm("cvt.rn.bf16x2.f32 %0, %1, %2;" : "=r"(lw) : "f"(y - fy), "f"(x - fx));
}

__device__ __forceinline__ void mma_bf16(float* d, const uint32_t* a,
                                         const uint32_t* b) {
    asm volatile(
        "mma.sync.aligned.m16n8k16.row.col.f32.bf16.bf16.f32 "
        "{%0,%1,%2,%3}, {%4,%5,%6,%7}, {%8,%9}, {%0,%1,%2,%3};"
        : "+f"(d[0]), "+f"(d[1]), "+f"(d[2]), "+f"(d[3])
        : "r"(a[0]), "r"(a[1]), "r"(a[2]), "r"(a[3]), "r"(b[0]), "r"(b[1]));
}

__device__ __forceinline__ int load_idx(const void* ei, long long pos) {
    if (g_is64) return (int)((const long long*)ei)[pos];
    return ((const int*)ei)[pos];
}

// ---------------------------------------------------------------------------
// Fused prep: edge dtype probe + zero counts + convert both weight matrices.
// All index spaces independent; grid covers max(NNODES, 128*128).
// ---------------------------------------------------------------------------
__global__ void k_prep(const int* __restrict__ ei32,
                       const float* __restrict__ W1,
                       const float* __restrict__ W2, int n) {
    int idx = blockIdx.x * blockDim.x + threadIdx.x;
    if (idx == 0) {
        int nz = 0;
#pragma unroll
        for (int i = 1; i < 64; i += 2) nz |= ei32[i];
        g_is64 = (nz == 0) ? 1 : 0;
    }
    if (idx < n) g_cnt[idx] = 0;
    if (idx < 128 * 128) {          // W1: K=256, KW=128
        int kp = idx % 128, nn = idx / 128;
        uint32_t hw, lw;
        bf16_split2(W1[(2 * kp) * 128 + nn], W1[(2 * kp + 1) * 128 + nn], hw, lw);
        g_w1h[idx] = hw; g_w1l[idx] = lw;
    }
    if (idx < 128 * 64) {           // W2: K=128, KW=64
        int kp = idx % 64, nn = idx / 64;
        uint32_t hw, lw;
        bf16_split2(W2[(2 * kp) * 128 + nn], W2[(2 * kp + 1) * 128 + nn], hw, lw);
        g_w2h[idx] = hw; g_w2l[idx] = lw;
    }
}

// ---------------------------------------------------------------------------
// CSR build: count -> blocksum(+dis) -> scan -> rowptr -> fill
// ---------------------------------------------------------------------------
__global__ void k_count(const void* __restrict__ ei, int E) {
    int e = blockIdx.x * blockDim.x + threadIdx.x;
    if (e < E) atomicAdd(&g_cnt[load_idx(ei, (long long)E + e)], 1);
}

__global__ void k_blocksum(int n) {
    __shared__ int sh[256];
    int t = threadIdx.x;
    int i = blockIdx.x * 256 + t;
    int c = (i < n) ? g_cnt[i] : 0;
    if (i < n) g_dis[i] = rsqrtf((float)(1 + c));
    sh[t] = c; __syncthreads();
#pragma unroll
    for (int off = 128; off > 0; off >>= 1) {
        if (t < off) sh[t] += sh[t + off];
        __syncthreads();
    }
    if (t == 0) g_bsum[blockIdx.x] = sh[0];
}

__global__ void k_scanbsum() {
    __shared__ int sh[256];
    int t = threadIdx.x;
    int v = (t < NBLK) ? g_bsum[t] : 0;
    sh[t] = v; __syncthreads();
#pragma unroll
    for (int off = 1; off < 256; off <<= 1) {
        int u = (t >= off) ? sh[t - off] : 0;
        __syncthreads();
        sh[t] += u;
        __syncthreads();
    }
    if (t < NBLK) g_boff[t] = sh[t] - v;
}

__global__ void k_rowptr(int n, int E) {
    __shared__ int sh[256];
    int t = threadIdx.x;
    int i = blockIdx.x * 256 + t;
    int c = (i < n) ? g_cnt[i] : 0;
    sh[t] = c; __syncthreads();
#pragma unroll
    for (int off = 1; off < 256; off <<= 1) {
        int u = (t >= off) ? sh[t - off] : 0;
        __syncthreads();
        sh[t] += u;
        __syncthreads();
    }
    if (i < n) {
        int val = g_boff[blockIdx.x] + sh[t] - c;
        g_rowptr[i] = val;
        g_cursor[i] = val;
        if (i == n - 1) g_rowptr[n] = E;
    }
}

__global__ void k_fill(const void* __restrict__ ei, int E) {
    int e = blockIdx.x * blockDim.x + threadIdx.x;
    if (e >= E) return;
    int s = load_idx(ei, e);
    int d = load_idx(ei, (long long)E + e);
    int pos = atomicAdd(&g_cursor[d], 1);
    g_csr[pos] = s;
}

// ---------------------------------------------------------------------------
// Pipelined tensor-core GEMM (bf16 hi/lo x3): g_hs = dis[i]*(A[M,K]@W[K,128]).
// Register double-buffer: next tile's LDGs issue right after syncthreads,
// overlapping memory latency with the 48-MMA compute phase.
// ---------------------------------------------------------------------------
#define AS_STRIDE 12
#define BS_STRIDE 12

template <int K, bool LAYER2>
__global__ __launch_bounds__(256) void k_gemm_bf16(
    const float* __restrict__ Ain, int M)
{
    const float* __restrict__ A = LAYER2 ? (const float*)g_x1 : Ain;
    const uint32_t* __restrict__ WH = LAYER2 ? g_w2h : g_w1h;
    const uint32_t* __restrict__ WL = LAYER2 ? g_w2l : g_w1l;
    constexpr int KW = K / 2;
    constexpr int NK = K / 16;

    __shared__ uint32_t Ash[128 * AS_STRIDE];
    __shared__ uint32_t Asl[128 * AS_STRIDE];
    __shared__ uint32_t Bsh[128 * BS_STRIDE];
    __shared__ uint32_t Bsl[128 * BS_STRIDE];

    const int tid    = threadIdx.x;
    const int lane   = tid & 31;
    const int wid    = tid >> 5;
    const int warp_m = wid & 3;
    const int warp_n = wid >> 2;
    const int qrow   = lane >> 2;
    const int qcol   = lane & 3;
    const int block_row = blockIdx.x * 128;

    // A load mapping: 2 float4 per thread
    const int ar0 = (tid * 2    ) >> 2, ac0 = (tid * 2    ) & 3;
    const int ar1 = (tid * 2 + 1) >> 2, ac1 = (tid * 2 + 1) & 3;
    // B load mapping: one uint4-pair per thread
    const int bn = tid >> 1;
    const int bw = (tid & 1) * 4;

    float acc[2][8][4];
#pragma unroll
    for (int mt = 0; mt < 2; mt++)
#pragma unroll
        for (int nt = 0; nt < 8; nt++)
#pragma unroll
            for (int r = 0; r < 4; r++) acc[mt][nt][r] = 0.0f;

    // Prologue: load tile 0 into registers
    float4 av0 = make_float4(0.f, 0.f, 0.f, 0.f);
    float4 av1 = make_float4(0.f, 0.f, 0.f, 0.f);
    uint4  bvh, bvl;
    {
        int g0 = block_row + ar0, g1 = block_row + ar1;
        if (g0 < M) av0 = reinterpret_cast<const float4*>(A + (size_t)g0 * K)[ac0];
        if (g1 < M) av1 = reinterpret_cast<const float4*>(A + (size_t)g1 * K)[ac1];
        bvh = reinterpret_cast<const uint4*>(WH + (size_t)bn * KW)[bw >> 2];
        bvl = reinterpret_cast<const uint4*>(WL + (size_t)bn * KW)[bw >> 2];
    }

    for (int kt = 0; kt < NK; kt++) {
        // Store current tile regs -> SMEM (A converted+split here)
        {
            uint32_t h0, l0, h1, l1;
            bf16_split2(av0.x, av0.y, h0, l0);
            bf16_split2(av0.z, av0.w, h1, l1);
            Ash[ar0 * AS_STRIDE + 2 * ac0    ] = h0;
            Ash[ar0 * AS_STRIDE + 2 * ac0 + 1] = h1;
            Asl[ar0 * AS_STRIDE + 2 * ac0    ] = l0;
            Asl[ar0 * AS_STRIDE + 2 * ac0 + 1] = l1;
            bf16_split2(av1.x, av1.y, h0, l0);
            bf16_split2(av1.z, av1.w, h1, l1);
            Ash[ar1 * AS_STRIDE + 2 * ac1    ] = h0;
            Ash[ar1 * AS_STRIDE + 2 * ac1 + 1] = h1;
            Asl[ar1 * AS_STRIDE + 2 * ac1    ] = l0;
            Asl[ar1 * AS_STRIDE + 2 * ac1 + 1] = l1;
            Bsh[bn * BS_STRIDE + bw + 0] = bvh.x;
            Bsh[bn * BS_STRIDE + bw + 1] = bvh.y;
            Bsh[bn * BS_STRIDE + bw + 2] = bvh.z;
            Bsh[bn * BS_STRIDE + bw + 3] = bvh.w;
            Bsl[bn * BS_STRIDE + bw + 0] = bvl.x;
            Bsl[bn * BS_STRIDE + bw + 1] = bvl.y;
            Bsl[bn * BS_STRIDE + bw + 2] = bvl.z;
            Bsl[bn * BS_STRIDE + bw + 3] = bvl.w;
        }
        __syncthreads();

        // Prefetch next tile (LDGs fly during the MMA phase below)
        if (kt + 1 < NK) {
            int k0 = (kt + 1) * 16;
            int g0 = block_row + ar0, g1 = block_row + ar1;
            av0 = make_float4(0.f, 0.f, 0.f, 0.f);
            av1 = make_float4(0.f, 0.f, 0.f, 0.f);
            if (g0 < M) av0 = reinterpret_cast<const float4*>(A + (size_t)g0 * K + k0)[ac0];
            if (g1 < M) av1 = reinterpret_cast<const float4*>(A + (size_t)g1 * K + k0)[ac1];
            bvh = reinterpret_cast<const uint4*>(WH + (size_t)bn * KW + k0 / 2)[bw >> 2];
            bvl = reinterpret_cast<const uint4*>(WL + (size_t)bn * KW + k0 / 2)[bw >> 2];
        }

        // Fragments + MMAs
        uint32_t ah[2][4], al[2][4];
#pragma unroll
        for (int mt = 0; mt < 2; mt++) {
            int r0 = warp_m * 32 + mt * 16 + qrow;
            ah[mt][0] = Ash[(r0    ) * AS_STRIDE + qcol    ];
            ah[mt][1] = Ash[(r0 + 8) * AS_STRIDE + qcol    ];
            ah[mt][2] = Ash[(r0    ) * AS_STRIDE + qcol + 4];
            ah[mt][3] = Ash[(r0 + 8) * AS_STRIDE + qcol + 4];
            al[mt][0] = Asl[(r0    ) * AS_STRIDE + qcol    ];
            al[mt][1] = Asl[(r0 + 8) * AS_STRIDE + qcol    ];
            al[mt][2] = Asl[(r0    ) * AS_STRIDE + qcol + 4];
            al[mt][3] = Asl[(r0 + 8) * AS_STRIDE + qcol + 4];
        }
#pragma unroll
        for (int nt = 0; nt < 8; nt++) {
            int n = warp_n * 64 + nt * 8 + qrow;
            uint32_t bh[2], bl[2];
            bh[0] = Bsh[n * BS_STRIDE + qcol    ];
            bh[1] = Bsh[n * BS_STRIDE + qcol + 4];
            bl[0] = Bsl[n * BS_STRIDE + qcol    ];
            bl[1] = Bsl[n * BS_STRIDE + qcol + 4];
#pragma unroll
            for (int mt = 0; mt < 2; mt++) {
                mma_bf16(acc[mt][nt], ah[mt], bl);
                mma_bf16(acc[mt][nt], al[mt], bh);
                mma_bf16(acc[mt][nt], ah[mt], bh);
            }
        }
        __syncthreads();
    }

    // Epilogue: scale rows by dis, store to g_hs
#pragma unroll
    for (int mt = 0; mt < 2; mt++) {
        int r0 = block_row + warp_m * 32 + mt * 16 + qrow;
        int r1 = r0 + 8;
        float d0 = (r0 < M) ? g_dis[r0] : 0.f;
        float d1 = (r1 < M) ? g_dis[r1] : 0.f;
#pragma unroll
        for (int nt = 0; nt < 8; nt++) {
            int c = warp_n * 64 + nt * 8 + 2 * qcol;
            if (r0 < M) {
                float2 v = make_float2(acc[mt][nt][0] * d0, acc[mt][nt][1] * d0);
                reinterpret_cast<float2*>(g_hs + (size_t)r0 * 128 + c)[0] = v;
            }
            if (r1 < M) {
                float2 v = make_float2(acc[mt][nt][2] * d1, acc[mt][nt][3] * d1);
                reinterpret_cast<float2*>(g_hs + (size_t)r1 * 128 + c)[0] = v;
            }
        }
    }
}

// ---------------------------------------------------------------------------
// CSR gather + fused finalize: one warp per node.
// ---------------------------------------------------------------------------
template <bool RELU, bool WRITE_X1>
__global__ __launch_bounds__(256) void k_gather(
    const float* __restrict__ b, float* __restrict__ out_arg, int M)
{
    float* __restrict__ out = WRITE_X1 ? (float*)g_x1 : out_arg;

    int w    = (blockIdx.x * 256 + threadIdx.x) >> 5;
    int lane = threadIdx.x & 31;
    if (w >= M) return;

    int start = g_rowptr[w];
    int end   = g_rowptr[w + 1];

    float4 acc = reinterpret_cast<const float4*>(g_hs + (size_t)w * 128)[lane];

    for (int chunk = start; chunk < end; chunk += 32) {
        int remaining = end - chunk;
        int cnt   = remaining < 32 ? remaining : 32;
        int myidx = (lane < cnt) ? g_csr[chunk + lane] : 0;
#pragma unroll 4
        for (int j = 0; j < cnt; j++) {
            int s = __shfl_sync(0xffffffffu, myidx, j);
            float4 v = reinterpret_cast<const float4*>(g_hs + (size_t)s * 128)[lane];
            acc.x += v.x; acc.y += v.y; acc.z += v.z; acc.w += v.w;
        }
    }

    float d = g_dis[w];
    float4 bb = reinterpret_cast<const float4*>(b)[lane];
    float4 r;
    r.x = fmaf(d, acc.x, bb.x);
    r.y = fmaf(d, acc.y, bb.y);
    r.z = fmaf(d, acc.z, bb.z);
    r.w = fmaf(d, acc.w, bb.w);
    if (RELU) {
        r.x = fmaxf(r.x, 0.f); r.y = fmaxf(r.y, 0.f);
        r.z = fmaxf(r.z, 0.f); r.w = fmaxf(r.w, 0.f);
    }
    reinterpret_cast<float4*>(out + (size_t)w * 128)[lane] = r;
}

// ---------------------------------------------------------------------------
extern "C" void kernel_launch(void* const* d_in, const int* in_sizes, int n_in,
                              void* d_out, int out_size)
{
    const float* x  = (const float*)d_in[0];       // [N, 256]
    const void*  ei = d_in[1];                     // [2, E] int32 (or int64)
    const float* W1 = (const float*)d_in[2];       // [256, 128]
    const float* b1 = (const float*)d_in[3];       // [128]
    const float* W2 = (const float*)d_in[4];       // [128, 128]
    const float* b2 = (const float*)d_in[5];       // [128]
    float*       out = (float*)d_out;              // [N, 128]

    const int M = in_sizes[0] / DIN;       // 50000
    const int E = in_sizes[1] / 2;         // 800000

    const int nblk   = (M + 255) / 256;
    const int eblk   = (E + 255) / 256;
    const int gemm_g = (M + 127) / 128;
    const int gath_g = (M * 32 + 255) / 256;

    // 0. fused prep (dtype probe + zero counts + weight convert)
    k_prep<<<nblk, 256>>>((const int*)ei, W1, W2, M);
    // 1. CSR build (+ dis)
    k_count<<<eblk, 256>>>(ei, E);
    k_blocksum<<<nblk, 256>>>(M);
    k_scanbsum<<<1, 256>>>();
    k_rowptr<<<nblk, 256>>>(M, E);
    k_fill<<<eblk, 256>>>(ei, E);

    // 2. layer 1
    k_gemm_bf16<DIN, false><<<gemm_g, 256>>>(x, M);
    k_gather<true, true><<<gath_g, 256>>>(b1, nullptr, M);

    // 3. layer 2
    k_gemm_bf16<DH, true><<<gemm_g, 256>>>(x, M);
    k_gather<false, false><<<gath_g, 256>>>(b2, out, M);
}

// round 14
// speedup vs baseline: 3.8420x; 1.0707x over previous
#include <cuda_runtime.h>
#include <cuda_bf16.h>
#include <stdint.h>

// Problem shape (fixed by the dataset)
#define NNODES   50000
#define DIN      256
#define DH       128
#define NBLK     ((NNODES + 255) / 256)     // 196

// Device scratch — referenced DIRECTLY from kernels (device code ONLY).
__device__ __align__(16) float g_dis[NNODES];           // rsqrt(1+deg)
__device__ __align__(16) float g_hs [NNODES * DH];      // UNscaled A@W rows
__device__ __align__(16) float g_x1 [NNODES * DH];      // layer-1 output
__device__ int g_cnt[NNODES];            // zero at entry of every call (see k_rowptr)
__device__ int g_rowptr[NNODES + 1];
__device__ int g_cursor[NNODES];
__device__ int g_csr[800000 + 1024];
__device__ int g_bsum[NBLK];
// Pre-converted weights: bf16x2-packed hi/lo, TRANSPOSED to [n][k/2] words.
__device__ __align__(16) uint32_t g_w1h[128 * 128];
__device__ __align__(16) uint32_t g_w1l[128 * 128];
__device__ __align__(16) uint32_t g_w2h[128 * 64];
__device__ __align__(16) uint32_t g_w2l[128 * 64];

// ---------------------------------------------------------------------------
// helpers
// ---------------------------------------------------------------------------
__device__ __forceinline__ void bf16_split2(float x, float y,
                                            uint32_t& hw, uint32_t& lw) {
    asm("cvt.rn.bf16x2.f32 %0, %1, %2;" : "=r"(hw) : "f"(y), "f"(x));
    float fx = __uint_as_float(hw << 16);
    float fy = __uint_as_float(hw & 0xffff0000u);
    asm("cvt.rn.bf16x2.f32 %0, %1, %2;" : "=r"(lw) : "f"(y - fy), "f"(x - fx));
}

__device__ __forceinline__ void mma_bf16(float* d, const uint32_t* a,
                                         const uint32_t* b) {
    asm volatile(
        "mma.sync.aligned.m16n8k16.row.col.f32.bf16.bf16.f32 "
        "{%0,%1,%2,%3}, {%4,%5,%6,%7}, {%8,%9}, {%0,%1,%2,%3};"
        : "+f"(d[0]), "+f"(d[1]), "+f"(d[2]), "+f"(d[3])
        : "r"(a[0]), "r"(a[1]), "r"(a[2]), "r"(a[3]), "r"(b[0]), "r"(b[1]));
}

// Inline edge-dtype probe: int64 edge data (<2^31) has odd words all zero.
__device__ __forceinline__ bool probe64(const int* ei32) {
    return (ei32[1] | ei32[3] | ei32[5] | ei32[7]) == 0;
}

// ---------------------------------------------------------------------------
// Weight pre-convert only (side-stream branch head)
// ---------------------------------------------------------------------------
__global__ void k_prep(const float* __restrict__ W1,
                       const float* __restrict__ W2) {
    int idx = blockIdx.x * blockDim.x + threadIdx.x;
    if (idx < 128 * 128) {          // W1: K=256, KW=128
        int kp = idx % 128, nn = idx / 128;
        uint32_t hw, lw;
        bf16_split2(W1[(2 * kp) * 128 + nn], W1[(2 * kp + 1) * 128 + nn], hw, lw);
        g_w1h[idx] = hw; g_w1l[idx] = lw;
    }
    if (idx < 128 * 64) {           // W2: K=128, KW=64
        int kp = idx % 64, nn = idx / 64;
        uint32_t hw, lw;
        bf16_split2(W2[(2 * kp) * 128 + nn], W2[(2 * kp + 1) * 128 + nn], hw, lw);
        g_w2h[idx] = hw; g_w2l[idx] = lw;
    }
}

// ---------------------------------------------------------------------------
// CSR build: count -> blocksum(+dis) -> rowptr(inline scan, re-zero cnt) -> fill
// ---------------------------------------------------------------------------
__global__ void k_count(const int* __restrict__ ei32, int E) {
    bool is64 = probe64(ei32);
    int e = blockIdx.x * blockDim.x + threadIdx.x;
    if (e < E) {
        int d = is64 ? (int)((const long long*)ei32)[(long long)E + e]
                     : ei32[E + e];
        atomicAdd(&g_cnt[d], 1);
    }
}

__global__ void k_blocksum(int n) {
    __shared__ int sh[256];
    int t = threadIdx.x;
    int i = blockIdx.x * 256 + t;
    int c = (i < n) ? g_cnt[i] : 0;
    if (i < n) g_dis[i] = rsqrtf((float)(1 + c));
    sh[t] = c; __syncthreads();
#pragma unroll
    for (int off = 128; off > 0; off >>= 1) {
        if (t < off) sh[t] += sh[t + off];
        __syncthreads();
    }
    if (t == 0) g_bsum[blockIdx.x] = sh[0];
}

__global__ void k_rowptr(int n, int E) {
    __shared__ int sh[256];
    __shared__ int boff_s;
    int t = threadIdx.x;
    int i = blockIdx.x * 256 + t;

    // inline exclusive scan over previous blocks' sums
    int partial = 0;
    for (int j = t; j < blockIdx.x; j += 256) partial += g_bsum[j];
    sh[t] = partial; __syncthreads();
#pragma unroll
    for (int off = 128; off > 0; off >>= 1) {
        if (t < off) sh[t] += sh[t + off];
        __syncthreads();
    }
    if (t == 0) boff_s = sh[0];
    __syncthreads();

    // intra-block inclusive scan of counts
    int c = (i < n) ? g_cnt[i] : 0;
    sh[t] = c; __syncthreads();
#pragma unroll
    for (int off = 1; off < 256; off <<= 1) {
        int u = (t >= off) ? sh[t - off] : 0;
        __syncthreads();
        sh[t] += u;
        __syncthreads();
    }
    if (i < n) {
        int val = boff_s + sh[t] - c;      // exclusive
        g_rowptr[i] = val;
        g_cursor[i] = val;
        g_cnt[i] = 0;                      // re-zero for NEXT invocation
        if (i == n - 1) g_rowptr[n] = E;
    }
}

__global__ void k_fill(const int* __restrict__ ei32, int E) {
    bool is64 = probe64(ei32);
    int e = blockIdx.x * blockDim.x + threadIdx.x;
    if (e >= E) return;
    int s, d;
    if (is64) {
        s = (int)((const long long*)ei32)[e];
        d = (int)((const long long*)ei32)[(long long)E + e];
    } else {
        s = ei32[e];
        d = ei32[E + e];
    }
    int pos = atomicAdd(&g_cursor[d], 1);
    g_csr[pos] = s;
}

// ---------------------------------------------------------------------------
// Pipelined tensor-core GEMM (bf16 hi/lo x3): g_hs = A[M,K] @ W[K,128].
// NO dis scaling (moved to gather) — GEMM has no dependency on the CSR branch.
// ---------------------------------------------------------------------------
#define AS_STRIDE 12
#define BS_STRIDE 12

template <int K, bool LAYER2>
__global__ __launch_bounds__(256) void k_gemm_bf16(
    const float* __restrict__ Ain, int M)
{
    const float* __restrict__ A = LAYER2 ? (const float*)g_x1 : Ain;
    const uint32_t* __restrict__ WH = LAYER2 ? g_w2h : g_w1h;
    const uint32_t* __restrict__ WL = LAYER2 ? g_w2l : g_w1l;
    constexpr int KW = K / 2;
    constexpr int NK = K / 16;

    __shared__ uint32_t Ash[128 * AS_STRIDE];
    __shared__ uint32_t Asl[128 * AS_STRIDE];
    __shared__ uint32_t Bsh[128 * BS_STRIDE];
    __shared__ uint32_t Bsl[128 * BS_STRIDE];

    const int tid    = threadIdx.x;
    const int lane   = tid & 31;
    const int wid    = tid >> 5;
    const int warp_m = wid & 3;
    const int warp_n = wid >> 2;
    const int qrow   = lane >> 2;
    const int qcol   = lane & 3;
    const int block_row = blockIdx.x * 128;

    const int ar0 = (tid * 2    ) >> 2, ac0 = (tid * 2    ) & 3;
    const int ar1 = (tid * 2 + 1) >> 2, ac1 = (tid * 2 + 1) & 3;
    const int bn = tid >> 1;
    const int bw = (tid & 1) * 4;

    float acc[2][8][4];
#pragma unroll
    for (int mt = 0; mt < 2; mt++)
#pragma unroll
        for (int nt = 0; nt < 8; nt++)
#pragma unroll
            for (int r = 0; r < 4; r++) acc[mt][nt][r] = 0.0f;

    float4 av0 = make_float4(0.f, 0.f, 0.f, 0.f);
    float4 av1 = make_float4(0.f, 0.f, 0.f, 0.f);
    uint4  bvh, bvl;
    {
        int g0 = block_row + ar0, g1 = block_row + ar1;
        if (g0 < M) av0 = reinterpret_cast<const float4*>(A + (size_t)g0 * K)[ac0];
        if (g1 < M) av1 = reinterpret_cast<const float4*>(A + (size_t)g1 * K)[ac1];
        bvh = reinterpret_cast<const uint4*>(WH + (size_t)bn * KW)[bw >> 2];
        bvl = reinterpret_cast<const uint4*>(WL + (size_t)bn * KW)[bw >> 2];
    }

    for (int kt = 0; kt < NK; kt++) {
        {
            uint32_t h0, l0, h1, l1;
            bf16_split2(av0.x, av0.y, h0, l0);
            bf16_split2(av0.z, av0.w, h1, l1);
            Ash[ar0 * AS_STRIDE + 2 * ac0    ] = h0;
            Ash[ar0 * AS_STRIDE + 2 * ac0 + 1] = h1;
            Asl[ar0 * AS_STRIDE + 2 * ac0    ] = l0;
            Asl[ar0 * AS_STRIDE + 2 * ac0 + 1] = l1;
            bf16_split2(av1.x, av1.y, h0, l0);
            bf16_split2(av1.z, av1.w, h1, l1);
            Ash[ar1 * AS_STRIDE + 2 * ac1    ] = h0;
            Ash[ar1 * AS_STRIDE + 2 * ac1 + 1] = h1;
            Asl[ar1 * AS_STRIDE + 2 * ac1    ] = l0;
            Asl[ar1 * AS_STRIDE + 2 * ac1 + 1] = l1;
            Bsh[bn * BS_STRIDE + bw + 0] = bvh.x;
            Bsh[bn * BS_STRIDE + bw + 1] = bvh.y;
            Bsh[bn * BS_STRIDE + bw + 2] = bvh.z;
            Bsh[bn * BS_STRIDE + bw + 3] = bvh.w;
            Bsl[bn * BS_STRIDE + bw + 0] = bvl.x;
            Bsl[bn * BS_STRIDE + bw + 1] = bvl.y;
            Bsl[bn * BS_STRIDE + bw + 2] = bvl.z;
            Bsl[bn * BS_STRIDE + bw + 3] = bvl.w;
        }
        __syncthreads();

        if (kt + 1 < NK) {
            int k0 = (kt + 1) * 16;
            int g0 = block_row + ar0, g1 = block_row + ar1;
            av0 = make_float4(0.f, 0.f, 0.f, 0.f);
            av1 = make_float4(0.f, 0.f, 0.f, 0.f);
            if (g0 < M) av0 = reinterpret_cast<const float4*>(A + (size_t)g0 * K + k0)[ac0];
            if (g1 < M) av1 = reinterpret_cast<const float4*>(A + (size_t)g1 * K + k0)[ac1];
            bvh = reinterpret_cast<const uint4*>(WH + (size_t)bn * KW + k0 / 2)[bw >> 2];
            bvl = reinterpret_cast<const uint4*>(WL + (size_t)bn * KW + k0 / 2)[bw >> 2];
        }

        uint32_t ah[2][4], al[2][4];
#pragma unroll
        for (int mt = 0; mt < 2; mt++) {
            int r0 = warp_m * 32 + mt * 16 + qrow;
            ah[mt][0] = Ash[(r0    ) * AS_STRIDE + qcol    ];
            ah[mt][1] = Ash[(r0 + 8) * AS_STRIDE + qcol    ];
            ah[mt][2] = Ash[(r0    ) * AS_STRIDE + qcol + 4];
            ah[mt][3] = Ash[(r0 + 8) * AS_STRIDE + qcol + 4];
            al[mt][0] = Asl[(r0    ) * AS_STRIDE + qcol    ];
            al[mt][1] = Asl[(r0 + 8) * AS_STRIDE + qcol    ];
            al[mt][2] = Asl[(r0    ) * AS_STRIDE + qcol + 4];
            al[mt][3] = Asl[(r0 + 8) * AS_STRIDE + qcol + 4];
        }
#pragma unroll
        for (int nt = 0; nt < 8; nt++) {
            int n = warp_n * 64 + nt * 8 + qrow;
            uint32_t bh[2], bl[2];
            bh[0] = Bsh[n * BS_STRIDE + qcol    ];
            bh[1] = Bsh[n * BS_STRIDE + qcol + 4];
            bl[0] = Bsl[n * BS_STRIDE + qcol    ];
            bl[1] = Bsl[n * BS_STRIDE + qcol + 4];
#pragma unroll
            for (int mt = 0; mt < 2; mt++) {
                mma_bf16(acc[mt][nt], ah[mt], bl);
                mma_bf16(acc[mt][nt], al[mt], bh);
                mma_bf16(acc[mt][nt], ah[mt], bh);
            }
        }
        __syncthreads();
    }

    // Epilogue: raw h -> g_hs
#pragma unroll
    for (int mt = 0; mt < 2; mt++) {
        int r0 = block_row + warp_m * 32 + mt * 16 + qrow;
        int r1 = r0 + 8;
#pragma unroll
        for (int nt = 0; nt < 8; nt++) {
            int c = warp_n * 64 + nt * 8 + 2 * qcol;
            if (r0 < M) {
                float2 v = make_float2(acc[mt][nt][0], acc[mt][nt][1]);
                reinterpret_cast<float2*>(g_hs + (size_t)r0 * 128 + c)[0] = v;
            }
            if (r1 < M) {
                float2 v = make_float2(acc[mt][nt][2], acc[mt][nt][3]);
                reinterpret_cast<float2*>(g_hs + (size_t)r1 * 128 + c)[0] = v;
            }
        }
    }
}

// ---------------------------------------------------------------------------
// CSR gather + dis weighting + fused finalize: one warp per node.
//   out[i] = dis[i] * ( dis[i]*h[i] + Σ dis[s]*h[s] ) + b     (+relu)
// ---------------------------------------------------------------------------
template <bool RELU, bool WRITE_X1>
__global__ __launch_bounds__(256) void k_gather(
    const float* __restrict__ b, float* __restrict__ out_arg, int M)
{
    float* __restrict__ out = WRITE_X1 ? (float*)g_x1 : out_arg;

    int w    = (blockIdx.x * 256 + threadIdx.x) >> 5;
    int lane = threadIdx.x & 31;
    if (w >= M) return;

    int start = g_rowptr[w];
    int end   = g_rowptr[w + 1];
    float dw  = g_dis[w];

    float4 acc = reinterpret_cast<const float4*>(g_hs + (size_t)w * 128)[lane];
    acc.x *= dw; acc.y *= dw; acc.z *= dw; acc.w *= dw;   // self loop: dis[w]*h[w]

    for (int chunk = start; chunk < end; chunk += 32) {
        int remaining = end - chunk;
        int cnt   = remaining < 32 ? remaining : 32;
        int   myidx = (lane < cnt) ? g_csr[chunk + lane] : 0;
        float myds  = (lane < cnt) ? g_dis[myidx] : 0.f;
#pragma unroll 4
        for (int j = 0; j < cnt; j++) {
            int   s  = __shfl_sync(0xffffffffu, myidx, j);
            float ds = __shfl_sync(0xffffffffu, myds,  j);
            float4 v = reinterpret_cast<const float4*>(g_hs + (size_t)s * 128)[lane];
            acc.x = fmaf(ds, v.x, acc.x);
            acc.y = fmaf(ds, v.y, acc.y);
            acc.z = fmaf(ds, v.z, acc.z);
            acc.w = fmaf(ds, v.w, acc.w);
        }
    }

    float4 bb = reinterpret_cast<const float4*>(b)[lane];
    float4 r;
    r.x = fmaf(dw, acc.x, bb.x);
    r.y = fmaf(dw, acc.y, bb.y);
    r.z = fmaf(dw, acc.z, bb.z);
    r.w = fmaf(dw, acc.w, bb.w);
    if (RELU) {
        r.x = fmaxf(r.x, 0.f); r.y = fmaxf(r.y, 0.f);
        r.z = fmaxf(r.z, 0.f); r.w = fmaxf(r.w, 0.f);
    }
    reinterpret_cast<float4*>(out + (size_t)w * 128)[lane] = r;
}

// ---------------------------------------------------------------------------
extern "C" void kernel_launch(void* const* d_in, const int* in_sizes, int n_in,
                              void* d_out, int out_size)
{
    const float* x  = (const float*)d_in[0];
    const int*   ei = (const int*)d_in[1];
    const float* W1 = (const float*)d_in[2];
    const float* b1 = (const float*)d_in[3];
    const float* W2 = (const float*)d_in[4];
    const float* b2 = (const float*)d_in[5];
    float*       out = (float*)d_out;

    const int M = in_sizes[0] / DIN;       // 50000
    const int E = in_sizes[1] / 2;         // 800000

    const int nblk   = (M + 255) / 256;
    const int eblk   = (E + 255) / 256;
    const int gemm_g = (M + 127) / 128;
    const int gath_g = (M * 32 + 255) / 256;

    // One-time stream/event creation (host objects only; identical captured
    // work every call — no device-memory allocation involved).
    static cudaStream_t s2 = nullptr;
    static cudaEvent_t  e_fork = nullptr, e_join = nullptr;
    if (!s2) {
        cudaStreamCreateWithFlags(&s2, cudaStreamNonBlocking);
        cudaEventCreateWithFlags(&e_fork, cudaEventDisableTiming);
        cudaEventCreateWithFlags(&e_join, cudaEventDisableTiming);
    }

    // Fork: side stream does weight prep + GEMM1 (independent of CSR/dis)
    cudaEventRecord(e_fork, 0);
    cudaStreamWaitEvent(s2, e_fork, 0);
    k_prep<<<64, 256, 0, s2>>>(W1, W2);
    k_gemm_bf16<DIN, false><<<gemm_g, 256, 0, s2>>>(x, M);
    cudaEventRecord(e_join, s2);

    // Main stream: CSR build (+ dis)
    k_count<<<eblk, 256>>>(ei, E);
    k_blocksum<<<nblk, 256>>>(M);
    k_rowptr<<<nblk, 256>>>(M, E);
    k_fill<<<eblk, 256>>>(ei, E);

    // Join, then the serial tail
    cudaStreamWaitEvent(0, e_join, 0);
    k_gather<true, true><<<gath_g, 256>>>(b1, nullptr, M);
    k_gemm_bf16<DH, true><<<gemm_g, 256>>>(x, M);
    k_gather<false, false><<<gath_g, 256>>>(b2, out, M);
}

// round 16
// speedup vs baseline: 3.8878x; 1.0119x over previous
#include <cuda_runtime.h>
#include <cuda_bf16.h>
#include <stdint.h>

// Problem shape (fixed by the dataset)
#define NNODES   50000
#define DIN      256
#define DH       128
#define NBLK     ((NNODES + 255) / 256)     // 196

// Device scratch — referenced DIRECTLY from kernels (device code ONLY).
__device__ __align__(16) float g_dis[NNODES];           // rsqrt(1+deg)
__device__ __align__(16) float g_hs [NNODES * DH];      // UNscaled A@W rows
__device__ __align__(16) float g_x1 [NNODES * DH];      // layer-1 output
__device__ int g_cnt[NNODES];            // zero at entry of every call (see k_rowptr)
__device__ int g_rowptr[NNODES + 1];
__device__ int g_cursor[NNODES];
__device__ int g_csr[800000 + 1024];
__device__ int g_bsum[NBLK];
// Pre-converted weights: bf16x2-packed hi/lo, TRANSPOSED to [n][k/2] words.
__device__ __align__(16) uint32_t g_w1h[128 * 128];
__device__ __align__(16) uint32_t g_w1l[128 * 128];
__device__ __align__(16) uint32_t g_w2h[128 * 64];
__device__ __align__(16) uint32_t g_w2l[128 * 64];

// ---------------------------------------------------------------------------
// helpers
// ---------------------------------------------------------------------------
__device__ __forceinline__ void bf16_split2(float x, float y,
                                            uint32_t& hw, uint32_t& lw) {
    asm("cvt.rn.bf16x2.f32 %0, %1, %2;" : "=r"(hw) : "f"(y), "f"(x));
    float fx = __uint_as_float(hw << 16);
    float fy = __uint_as_float(hw & 0xffff0000u);
    asm("cvt.rn.bf16x2.f32 %0, %1, %2;" : "=r"(lw) : "f"(y - fy), "f"(x - fx));
}

__device__ __forceinline__ void mma_bf16(float* d, const uint32_t* a,
                                         const uint32_t* b) {
    asm volatile(
        "mma.sync.aligned.m16n8k16.row.col.f32.bf16.bf16.f32 "
        "{%0,%1,%2,%3}, {%4,%5,%6,%7}, {%8,%9}, {%0,%1,%2,%3};"
        : "+f"(d[0]), "+f"(d[1]), "+f"(d[2]), "+f"(d[3])
        : "r"(a[0]), "r"(a[1]), "r"(a[2]), "r"(a[3]), "r"(b[0]), "r"(b[1]));
}

__device__ __forceinline__ bool probe64(const int* ei32) {
    return (ei32[1] | ei32[3] | ei32[5] | ei32[7]) == 0;
}

// ---------------------------------------------------------------------------
// Weight pre-convert (side-stream branch head)
// ---------------------------------------------------------------------------
__global__ void k_prep(const float* __restrict__ W1,
                       const float* __restrict__ W2) {
    int idx = blockIdx.x * blockDim.x + threadIdx.x;
    if (idx < 128 * 128) {          // W1: K=256, KW=128
        int kp = idx % 128, nn = idx / 128;
        uint32_t hw, lw;
        bf16_split2(W1[(2 * kp) * 128 + nn], W1[(2 * kp + 1) * 128 + nn], hw, lw);
        g_w1h[idx] = hw; g_w1l[idx] = lw;
    }
    if (idx < 128 * 64) {           // W2: K=128, KW=64
        int kp = idx % 64, nn = idx / 64;
        uint32_t hw, lw;
        bf16_split2(W2[(2 * kp) * 128 + nn], W2[(2 * kp + 1) * 128 + nn], hw, lw);
        g_w2h[idx] = hw; g_w2l[idx] = lw;
    }
}

// ---------------------------------------------------------------------------
// CSR build: count -> blocksum(+dis) -> rowptr(inline scan, re-zero cnt) -> fill
// ---------------------------------------------------------------------------
__global__ void k_count(const int* __restrict__ ei32, int E) {
    bool is64 = probe64(ei32);
    int e = blockIdx.x * blockDim.x + threadIdx.x;
    if (e < E) {
        int d = is64 ? (int)((const long long*)ei32)[(long long)E + e]
                     : ei32[E + e];
        atomicAdd(&g_cnt[d], 1);
    }
}

__global__ void k_blocksum(int n) {
    __shared__ int sh[256];
    int t = threadIdx.x;
    int i = blockIdx.x * 256 + t;
    int c = (i < n) ? g_cnt[i] : 0;
    if (i < n) g_dis[i] = rsqrtf((float)(1 + c));
    sh[t] = c; __syncthreads();
#pragma unroll
    for (int off = 128; off > 0; off >>= 1) {
        if (t < off) sh[t] += sh[t + off];
        __syncthreads();
    }
    if (t == 0) g_bsum[blockIdx.x] = sh[0];
}

__global__ void k_rowptr(int n, int E) {
    __shared__ int sh[256];
    __shared__ int boff_s;
    int t = threadIdx.x;
    int i = blockIdx.x * 256 + t;

    int partial = 0;
    for (int j = t; j < blockIdx.x; j += 256) partial += g_bsum[j];
    sh[t] = partial; __syncthreads();
#pragma unroll
    for (int off = 128; off > 0; off >>= 1) {
        if (t < off) sh[t] += sh[t + off];
        __syncthreads();
    }
    if (t == 0) boff_s = sh[0];
    __syncthreads();

    int c = (i < n) ? g_cnt[i] : 0;
    sh[t] = c; __syncthreads();
#pragma unroll
    for (int off = 1; off < 256; off <<= 1) {
        int u = (t >= off) ? sh[t - off] : 0;
        __syncthreads();
        sh[t] += u;
        __syncthreads();
    }
    if (i < n) {
        int val = boff_s + sh[t] - c;
        g_rowptr[i] = val;
        g_cursor[i] = val;
        g_cnt[i] = 0;                      // re-zero for NEXT invocation
        if (i == n - 1) g_rowptr[n] = E;
    }
}

__global__ void k_fill(const int* __restrict__ ei32, int E) {
    bool is64 = probe64(ei32);
    int e = blockIdx.x * blockDim.x + threadIdx.x;
    if (e >= E) return;
    int s, d;
    if (is64) {
        s = (int)((const long long*)ei32)[e];
        d = (int)((const long long*)ei32)[(long long)E + e];
    } else {
        s = ei32[e];
        d = ei32[E + e];
    }
    int pos = atomicAdd(&g_cursor[d], 1);
    g_csr[pos] = s;
}

// ---------------------------------------------------------------------------
// Pipelined tensor-core GEMM (bf16 hi/lo x3): g_hs = A[M,K] @ W[K,128].
// block_off allows row-partitioned grids (layer-2 pipeline).
// ---------------------------------------------------------------------------
#define AS_STRIDE 12
#define BS_STRIDE 12

template <int K, bool LAYER2>
__global__ __launch_bounds__(256) void k_gemm_bf16(
    const float* __restrict__ Ain, int M, int block_off)
{
    const float* __restrict__ A = LAYER2 ? (const float*)g_x1 : Ain;
    const uint32_t* __restrict__ WH = LAYER2 ? g_w2h : g_w1h;
    const uint32_t* __restrict__ WL = LAYER2 ? g_w2l : g_w1l;
    constexpr int KW = K / 2;
    constexpr int NK = K / 16;

    __shared__ uint32_t Ash[128 * AS_STRIDE];
    __shared__ uint32_t Asl[128 * AS_STRIDE];
    __shared__ uint32_t Bsh[128 * BS_STRIDE];
    __shared__ uint32_t Bsl[128 * BS_STRIDE];

    const int tid    = threadIdx.x;
    const int lane   = tid & 31;
    const int wid    = tid >> 5;
    const int warp_m = wid & 3;
    const int warp_n = wid >> 2;
    const int qrow   = lane >> 2;
    const int qcol   = lane & 3;
    const int block_row = (blockIdx.x + block_off) * 128;

    const int ar0 = (tid * 2    ) >> 2, ac0 = (tid * 2    ) & 3;
    const int ar1 = (tid * 2 + 1) >> 2, ac1 = (tid * 2 + 1) & 3;
    const int bn = tid >> 1;
    const int bw = (tid & 1) * 4;

    float acc[2][8][4];
#pragma unroll
    for (int mt = 0; mt < 2; mt++)
#pragma unroll
        for (int nt = 0; nt < 8; nt++)
#pragma unroll
            for (int r = 0; r < 4; r++) acc[mt][nt][r] = 0.0f;

    float4 av0 = make_float4(0.f, 0.f, 0.f, 0.f);
    float4 av1 = make_float4(0.f, 0.f, 0.f, 0.f);
    uint4  bvh, bvl;
    {
        int g0 = block_row + ar0, g1 = block_row + ar1;
        if (g0 < M) av0 = reinterpret_cast<const float4*>(A + (size_t)g0 * K)[ac0];
        if (g1 < M) av1 = reinterpret_cast<const float4*>(A + (size_t)g1 * K)[ac1];
        bvh = reinterpret_cast<const uint4*>(WH + (size_t)bn * KW)[bw >> 2];
        bvl = reinterpret_cast<const uint4*>(WL + (size_t)bn * KW)[bw >> 2];
    }

    for (int kt = 0; kt < NK; kt++) {
        {
            uint32_t h0, l0, h1, l1;
            bf16_split2(av0.x, av0.y, h0, l0);
            bf16_split2(av0.z, av0.w, h1, l1);
            Ash[ar0 * AS_STRIDE + 2 * ac0    ] = h0;
            Ash[ar0 * AS_STRIDE + 2 * ac0 + 1] = h1;
            Asl[ar0 * AS_STRIDE + 2 * ac0    ] = l0;
            Asl[ar0 * AS_STRIDE + 2 * ac0 + 1] = l1;
            bf16_split2(av1.x, av1.y, h0, l0);
            bf16_split2(av1.z, av1.w, h1, l1);
            Ash[ar1 * AS_STRIDE + 2 * ac1    ] = h0;
            Ash[ar1 * AS_STRIDE + 2 * ac1 + 1] = h1;
            Asl[ar1 * AS_STRIDE + 2 * ac1    ] = l0;
            Asl[ar1 * AS_STRIDE + 2 * ac1 + 1] = l1;
            Bsh[bn * BS_STRIDE + bw + 0] = bvh.x;
            Bsh[bn * BS_STRIDE + bw + 1] = bvh.y;
            Bsh[bn * BS_STRIDE + bw + 2] = bvh.z;
            Bsh[bn * BS_STRIDE + bw + 3] = bvh.w;
            Bsl[bn * BS_STRIDE + bw + 0] = bvl.x;
            Bsl[bn * BS_STRIDE + bw + 1] = bvl.y;
            Bsl[bn * BS_STRIDE + bw + 2] = bvl.z;
            Bsl[bn * BS_STRIDE + bw + 3] = bvl.w;
        }
        __syncthreads();

        if (kt + 1 < NK) {
            int k0 = (kt + 1) * 16;
            int g0 = block_row + ar0, g1 = block_row + ar1;
            av0 = make_float4(0.f, 0.f, 0.f, 0.f);
            av1 = make_float4(0.f, 0.f, 0.f, 0.f);
            if (g0 < M) av0 = reinterpret_cast<const float4*>(A + (size_t)g0 * K + k0)[ac0];
            if (g1 < M) av1 = reinterpret_cast<const float4*>(A + (size_t)g1 * K + k0)[ac1];
            bvh = reinterpret_cast<const uint4*>(WH + (size_t)bn * KW + k0 / 2)[bw >> 2];
            bvl = reinterpret_cast<const uint4*>(WL + (size_t)bn * KW + k0 / 2)[bw >> 2];
        }

        uint32_t ah[2][4], al[2][4];
#pragma unroll
        for (int mt = 0; mt < 2; mt++) {
            int r0 = warp_m * 32 + mt * 16 + qrow;
            ah[mt][0] = Ash[(r0    ) * AS_STRIDE + qcol    ];
            ah[mt][1] = Ash[(r0 + 8) * AS_STRIDE + qcol    ];
            ah[mt][2] = Ash[(r0    ) * AS_STRIDE + qcol + 4];
            ah[mt][3] = Ash[(r0 + 8) * AS_STRIDE + qcol + 4];
            al[mt][0] = Asl[(r0    ) * AS_STRIDE + qcol    ];
            al[mt][1] = Asl[(r0 + 8) * AS_STRIDE + qcol    ];
            al[mt][2] = Asl[(r0    ) * AS_STRIDE + qcol + 4];
            al[mt][3] = Asl[(r0 + 8) * AS_STRIDE + qcol + 4];
        }
#pragma unroll
        for (int nt = 0; nt < 8; nt++) {
            int n = warp_n * 64 + nt * 8 + qrow;
            uint32_t bh[2], bl[2];
            bh[0] = Bsh[n * BS_STRIDE + qcol    ];
            bh[1] = Bsh[n * BS_STRIDE + qcol + 4];
            bl[0] = Bsl[n * BS_STRIDE + qcol    ];
            bl[1] = Bsl[n * BS_STRIDE + qcol + 4];
#pragma unroll
            for (int mt = 0; mt < 2; mt++) {
                mma_bf16(acc[mt][nt], ah[mt], bl);
                mma_bf16(acc[mt][nt], al[mt], bh);
                mma_bf16(acc[mt][nt], ah[mt], bh);
            }
        }
        __syncthreads();
    }

#pragma unroll
    for (int mt = 0; mt < 2; mt++) {
        int r0 = block_row + warp_m * 32 + mt * 16 + qrow;
        int r1 = r0 + 8;
#pragma unroll
        for (int nt = 0; nt < 8; nt++) {
            int c = warp_n * 64 + nt * 8 + 2 * qcol;
            if (r0 < M) {
                float2 v = make_float2(acc[mt][nt][0], acc[mt][nt][1]);
                reinterpret_cast<float2*>(g_hs + (size_t)r0 * 128 + c)[0] = v;
            }
            if (r1 < M) {
                float2 v = make_float2(acc[mt][nt][2], acc[mt][nt][3]);
                reinterpret_cast<float2*>(g_hs + (size_t)r1 * 128 + c)[0] = v;
            }
        }
    }
}

// ---------------------------------------------------------------------------
// CSR gather + dis weighting + fused finalize: one warp per node, node range
// [node_off, node_end) for the row-split pipeline.
// ---------------------------------------------------------------------------
template <bool RELU, bool WRITE_X1>
__global__ __launch_bounds__(256) void k_gather(
    const float* __restrict__ b, float* __restrict__ out_arg,
    int node_off, int node_end)
{
    float* __restrict__ out = WRITE_X1 ? (float*)g_x1 : out_arg;

    int w    = node_off + ((blockIdx.x * 256 + threadIdx.x) >> 5);
    int lane = threadIdx.x & 31;
    if (w >= node_end) return;

    int start = g_rowptr[w];
    int end   = g_rowptr[w + 1];
    float dw  = g_dis[w];

    float4 acc = reinterpret_cast<const float4*>(g_hs + (size_t)w * 128)[lane];
    acc.x *= dw; acc.y *= dw; acc.z *= dw; acc.w *= dw;

    for (int chunk = start; chunk < end; chunk += 32) {
        int remaining = end - chunk;
        int cnt   = remaining < 32 ? remaining : 32;
        int   myidx = (lane < cnt) ? g_csr[chunk + lane] : 0;
        float myds  = (lane < cnt) ? g_dis[myidx] : 0.f;
#pragma unroll 4
        for (int j = 0; j < cnt; j++) {
            int   s  = __shfl_sync(0xffffffffu, myidx, j);
            float ds = __shfl_sync(0xffffffffu, myds,  j);
            float4 v = reinterpret_cast<const float4*>(g_hs + (size_t)s * 128)[lane];
            acc.x = fmaf(ds, v.x, acc.x);
            acc.y = fmaf(ds, v.y, acc.y);
            acc.z = fmaf(ds, v.z, acc.z);
            acc.w = fmaf(ds, v.w, acc.w);
        }
    }

    float4 bb = reinterpret_cast<const float4*>(b)[lane];
    float4 r;
    r.x = fmaf(dw, acc.x, bb.x);
    r.y = fmaf(dw, acc.y, bb.y);
    r.z = fmaf(dw, acc.z, bb.z);
    r.w = fmaf(dw, acc.w, bb.w);
    if (RELU) {
        r.x = fmaxf(r.x, 0.f); r.y = fmaxf(r.y, 0.f);
        r.z = fmaxf(r.z, 0.f); r.w = fmaxf(r.w, 0.f);
    }
    reinterpret_cast<float4*>(out + (size_t)w * 128)[lane] = r;
}

// ---------------------------------------------------------------------------
extern "C" void kernel_launch(void* const* d_in, const int* in_sizes, int n_in,
                              void* d_out, int out_size)
{
    const float* x  = (const float*)d_in[0];
    const int*   ei = (const int*)d_in[1];
    const float* W1 = (const float*)d_in[2];
    const float* b1 = (const float*)d_in[3];
    const float* W2 = (const float*)d_in[4];
    const float* b2 = (const float*)d_in[5];
    float*       out = (float*)d_out;

    const int M = in_sizes[0] / DIN;       // 50000
    const int E = in_sizes[1] / 2;         // 800000

    const int nblk   = (M + 255) / 256;
    const int eblk   = (E + 255) / 256;
    const int gemm_g = (M + 127) / 128;            // 391
    const int Ga     = (gemm_g + 1) / 2;           // 196 row-blocks (half A)
    const int Gb     = gemm_g - Ga;                // 195
    const int SPLIT  = Ga * 128;                   // 25088 (row split point)
    const int ga_g   = (SPLIT * 32 + 255) / 256;
    const int gb_g   = ((M - SPLIT) * 32 + 255) / 256;
    const int gath_g = (M * 32 + 255) / 256;

    static cudaStream_t s2 = nullptr;
    static cudaEvent_t  e_fork = nullptr, e_g1 = nullptr, e_csr = nullptr, e_b = nullptr;
    if (!s2) {
        cudaStreamCreateWithFlags(&s2, cudaStreamNonBlocking);
        cudaEventCreateWithFlags(&e_fork, cudaEventDisableTiming);
        cudaEventCreateWithFlags(&e_g1,   cudaEventDisableTiming);
        cudaEventCreateWithFlags(&e_csr,  cudaEventDisableTiming);
        cudaEventCreateWithFlags(&e_b,    cudaEventDisableTiming);
    }

    // Fork: side stream = weight prep + GEMM1 (independent of CSR/dis)
    cudaEventRecord(e_fork, 0);
    cudaStreamWaitEvent(s2, e_fork, 0);
    k_prep<<<64, 256, 0, s2>>>(W1, W2);
    k_gemm_bf16<DIN, false><<<gemm_g, 256, 0, s2>>>(x, M, 0);
    cudaEventRecord(e_g1, s2);

    // Main stream: CSR build (+ dis)
    k_count<<<eblk, 256>>>(ei, E);
    k_blocksum<<<nblk, 256>>>(M);
    k_rowptr<<<nblk, 256>>>(M, E);
    k_fill<<<eblk, 256>>>(ei, E);
    cudaEventRecord(e_csr, 0);

    // Row-split pipeline for layer 1 gather -> layer 2 GEMM:
    //   main: gather1a -> GEMM2a            (rows [0, SPLIT))
    //   s2:   gather1b -> GEMM2b -> e_b     (rows [SPLIT, M))
    cudaStreamWaitEvent(0, e_g1, 0);
    cudaStreamWaitEvent(s2, e_csr, 0);

    k_gather<true, true><<<ga_g, 256>>>(b1, nullptr, 0, SPLIT);
    k_gemm_bf16<DH, true><<<Ga, 256>>>(x, M, 0);

    k_gather<true, true><<<gb_g, 256, 0, s2>>>(b1, nullptr, SPLIT, M);
    k_gemm_bf16<DH, true><<<Gb, 256, 0, s2>>>(x, M, Ga);
    cudaEventRecord(e_b, s2);

    // Join, then final gather into d_out
    cudaStreamWaitEvent(0, e_b, 0);
    k_gather<false, false><<<gath_g, 256>>>(b2, out, 0, M);
}

// round 17
// speedup vs baseline: 4.0166x; 1.0331x over previous
#include <cuda_runtime.h>
#include <cuda_bf16.h>
#include <cuda_fp16.h>
#include <stdint.h>

// Problem shape (fixed by the dataset)
#define NNODES   50000
#define DIN      256
#define DH       128
#define NBLK     ((NNODES + 255) / 256)     // 196

// Device scratch — referenced DIRECTLY from kernels (device code ONLY).
__device__ __align__(16) float    g_dis[NNODES];          // rsqrt(1+deg)
__device__ __align__(16) uint32_t g_hs16[NNODES * 64];    // A@W rows, fp16x2 packed
__device__ __align__(16) float    g_x1 [NNODES * DH];     // layer-1 output (fp32)
__device__ int g_cnt[NNODES];            // zero at entry of every call (see k_rowptr)
__device__ int g_rowptr[NNODES + 1];
__device__ int g_cursor[NNODES];
__device__ int g_csr[800000 + 1024];
__device__ int g_bsum[NBLK];
// Pre-converted weights: bf16x2-packed hi/lo, TRANSPOSED to [n][k/2] words.
__device__ __align__(16) uint32_t g_w1h[128 * 128];
__device__ __align__(16) uint32_t g_w1l[128 * 128];
__device__ __align__(16) uint32_t g_w2h[128 * 64];
__device__ __align__(16) uint32_t g_w2l[128 * 64];

// ---------------------------------------------------------------------------
// helpers
// ---------------------------------------------------------------------------
__device__ __forceinline__ void bf16_split2(float x, float y,
                                            uint32_t& hw, uint32_t& lw) {
    asm("cvt.rn.bf16x2.f32 %0, %1, %2;" : "=r"(hw) : "f"(y), "f"(x));
    float fx = __uint_as_float(hw << 16);
    float fy = __uint_as_float(hw & 0xffff0000u);
    asm("cvt.rn.bf16x2.f32 %0, %1, %2;" : "=r"(lw) : "f"(y - fy), "f"(x - fx));
}

__device__ __forceinline__ uint32_t pack_f16x2(float lo, float hi) {
    uint32_t p;
    asm("cvt.rn.f16x2.f32 %0, %1, %2;" : "=r"(p) : "f"(hi), "f"(lo));
    return p;
}

__device__ __forceinline__ float2 unpack_f16x2(uint32_t w) {
    __half2 h = *reinterpret_cast<__half2*>(&w);
    return __half22float2(h);
}

__device__ __forceinline__ void mma_bf16(float* d, const uint32_t* a,
                                         const uint32_t* b) {
    asm volatile(
        "mma.sync.aligned.m16n8k16.row.col.f32.bf16.bf16.f32 "
        "{%0,%1,%2,%3}, {%4,%5,%6,%7}, {%8,%9}, {%0,%1,%2,%3};"
        : "+f"(d[0]), "+f"(d[1]), "+f"(d[2]), "+f"(d[3])
        : "r"(a[0]), "r"(a[1]), "r"(a[2]), "r"(a[3]), "r"(b[0]), "r"(b[1]));
}

__device__ __forceinline__ bool probe64(const int* ei32) {
    return (ei32[1] | ei32[3] | ei32[5] | ei32[7]) == 0;
}

// ---------------------------------------------------------------------------
// Weight pre-convert (side-stream branch head)
// ---------------------------------------------------------------------------
__global__ void k_prep(const float* __restrict__ W1,
                       const float* __restrict__ W2) {
    int idx = blockIdx.x * blockDim.x + threadIdx.x;
    if (idx < 128 * 128) {          // W1: K=256, KW=128
        int kp = idx % 128, nn = idx / 128;
        uint32_t hw, lw;
        bf16_split2(W1[(2 * kp) * 128 + nn], W1[(2 * kp + 1) * 128 + nn], hw, lw);
        g_w1h[idx] = hw; g_w1l[idx] = lw;
    }
    if (idx < 128 * 64) {           // W2: K=128, KW=64
        int kp = idx % 64, nn = idx / 64;
        uint32_t hw, lw;
        bf16_split2(W2[(2 * kp) * 128 + nn], W2[(2 * kp + 1) * 128 + nn], hw, lw);
        g_w2h[idx] = hw; g_w2l[idx] = lw;
    }
}

// ---------------------------------------------------------------------------
// CSR build: count -> blocksum(+dis) -> rowptr(inline scan, re-zero cnt) -> fill
// ---------------------------------------------------------------------------
__global__ void k_count(const int* __restrict__ ei32, int E) {
    bool is64 = probe64(ei32);
    int e = blockIdx.x * blockDim.x + threadIdx.x;
    if (e < E) {
        int d = is64 ? (int)((const long long*)ei32)[(long long)E + e]
                     : ei32[E + e];
        atomicAdd(&g_cnt[d], 1);
    }
}

__global__ void k_blocksum(int n) {
    __shared__ int sh[256];
    int t = threadIdx.x;
    int i = blockIdx.x * 256 + t;
    int c = (i < n) ? g_cnt[i] : 0;
    if (i < n) g_dis[i] = rsqrtf((float)(1 + c));
    sh[t] = c; __syncthreads();
#pragma unroll
    for (int off = 128; off > 0; off >>= 1) {
        if (t < off) sh[t] += sh[t + off];
        __syncthreads();
    }
    if (t == 0) g_bsum[blockIdx.x] = sh[0];
}

__global__ void k_rowptr(int n, int E) {
    __shared__ int sh[256];
    __shared__ int boff_s;
    int t = threadIdx.x;
    int i = blockIdx.x * 256 + t;

    int partial = 0;
    for (int j = t; j < blockIdx.x; j += 256) partial += g_bsum[j];
    sh[t] = partial; __syncthreads();
#pragma unroll
    for (int off = 128; off > 0; off >>= 1) {
        if (t < off) sh[t] += sh[t + off];
        __syncthreads();
    }
    if (t == 0) boff_s = sh[0];
    __syncthreads();

    int c = (i < n) ? g_cnt[i] : 0;
    sh[t] = c; __syncthreads();
#pragma unroll
    for (int off = 1; off < 256; off <<= 1) {
        int u = (t >= off) ? sh[t - off] : 0;
        __syncthreads();
        sh[t] += u;
        __syncthreads();
    }
    if (i < n) {
        int val = boff_s + sh[t] - c;
        g_rowptr[i] = val;
        g_cursor[i] = val;
        g_cnt[i] = 0;                      // re-zero for NEXT invocation
        if (i == n - 1) g_rowptr[n] = E;
    }
}

__global__ void k_fill(const int* __restrict__ ei32, int E) {
    bool is64 = probe64(ei32);
    int e = blockIdx.x * blockDim.x + threadIdx.x;
    if (e >= E) return;
    int s, d;
    if (is64) {
        s = (int)((const long long*)ei32)[e];
        d = (int)((const long long*)ei32)[(long long)E + e];
    } else {
        s = ei32[e];
        d = ei32[E + e];
    }
    int pos = atomicAdd(&g_cursor[d], 1);
    g_csr[pos] = s;
}

// ---------------------------------------------------------------------------
// Pipelined tensor-core GEMM (bf16 hi/lo x3): g_hs16 = fp16(A[M,K] @ W[K,128]).
// block_off allows row-partitioned grids (layer-2 pipeline).
// ---------------------------------------------------------------------------
#define AS_STRIDE 12
#define BS_STRIDE 12

template <int K, bool LAYER2>
__global__ __launch_bounds__(256) void k_gemm_bf16(
    const float* __restrict__ Ain, int M, int block_off)
{
    const float* __restrict__ A = LAYER2 ? (const float*)g_x1 : Ain;
    const uint32_t* __restrict__ WH = LAYER2 ? g_w2h : g_w1h;
    const uint32_t* __restrict__ WL = LAYER2 ? g_w2l : g_w1l;
    constexpr int KW = K / 2;
    constexpr int NK = K / 16;

    __shared__ uint32_t Ash[128 * AS_STRIDE];
    __shared__ uint32_t Asl[128 * AS_STRIDE];
    __shared__ uint32_t Bsh[128 * BS_STRIDE];
    __shared__ uint32_t Bsl[128 * BS_STRIDE];

    const int tid    = threadIdx.x;
    const int lane   = tid & 31;
    const int wid    = tid >> 5;
    const int warp_m = wid & 3;
    const int warp_n = wid >> 2;
    const int qrow   = lane >> 2;
    const int qcol   = lane & 3;
    const int block_row = (blockIdx.x + block_off) * 128;

    const int ar0 = (tid * 2    ) >> 2, ac0 = (tid * 2    ) & 3;
    const int ar1 = (tid * 2 + 1) >> 2, ac1 = (tid * 2 + 1) & 3;
    const int bn = tid >> 1;
    const int bw = (tid & 1) * 4;

    float acc[2][8][4];
#pragma unroll
    for (int mt = 0; mt < 2; mt++)
#pragma unroll
        for (int nt = 0; nt < 8; nt++)
#pragma unroll
            for (int r = 0; r < 4; r++) acc[mt][nt][r] = 0.0f;

    float4 av0 = make_float4(0.f, 0.f, 0.f, 0.f);
    float4 av1 = make_float4(0.f, 0.f, 0.f, 0.f);
    uint4  bvh, bvl;
    {
        int g0 = block_row + ar0, g1 = block_row + ar1;
        if (g0 < M) av0 = reinterpret_cast<const float4*>(A + (size_t)g0 * K)[ac0];
        if (g1 < M) av1 = reinterpret_cast<const float4*>(A + (size_t)g1 * K)[ac1];
        bvh = reinterpret_cast<const uint4*>(WH + (size_t)bn * KW)[bw >> 2];
        bvl = reinterpret_cast<const uint4*>(WL + (size_t)bn * KW)[bw >> 2];
    }

    for (int kt = 0; kt < NK; kt++) {
        {
            uint32_t h0, l0, h1, l1;
            bf16_split2(av0.x, av0.y, h0, l0);
            bf16_split2(av0.z, av0.w, h1, l1);
            Ash[ar0 * AS_STRIDE + 2 * ac0    ] = h0;
            Ash[ar0 * AS_STRIDE + 2 * ac0 + 1] = h1;
            Asl[ar0 * AS_STRIDE + 2 * ac0    ] = l0;
            Asl[ar0 * AS_STRIDE + 2 * ac0 + 1] = l1;
            bf16_split2(av1.x, av1.y, h0, l0);
            bf16_split2(av1.z, av1.w, h1, l1);
            Ash[ar1 * AS_STRIDE + 2 * ac1    ] = h0;
            Ash[ar1 * AS_STRIDE + 2 * ac1 + 1] = h1;
            Asl[ar1 * AS_STRIDE + 2 * ac1    ] = l0;
            Asl[ar1 * AS_STRIDE + 2 * ac1 + 1] = l1;
            Bsh[bn * BS_STRIDE + bw + 0] = bvh.x;
            Bsh[bn * BS_STRIDE + bw + 1] = bvh.y;
            Bsh[bn * BS_STRIDE + bw + 2] = bvh.z;
            Bsh[bn * BS_STRIDE + bw + 3] = bvh.w;
            Bsl[bn * BS_STRIDE + bw + 0] = bvl.x;
            Bsl[bn * BS_STRIDE + bw + 1] = bvl.y;
            Bsl[bn * BS_STRIDE + bw + 2] = bvl.z;
            Bsl[bn * BS_STRIDE + bw + 3] = bvl.w;
        }
        __syncthreads();

        if (kt + 1 < NK) {
            int k0 = (kt + 1) * 16;
            int g0 = block_row + ar0, g1 = block_row + ar1;
            av0 = make_float4(0.f, 0.f, 0.f, 0.f);
            av1 = make_float4(0.f, 0.f, 0.f, 0.f);
            if (g0 < M) av0 = reinterpret_cast<const float4*>(A + (size_t)g0 * K + k0)[ac0];
            if (g1 < M) av1 = reinterpret_cast<const float4*>(A + (size_t)g1 * K + k0)[ac1];
            bvh = reinterpret_cast<const uint4*>(WH + (size_t)bn * KW + k0 / 2)[bw >> 2];
            bvl = reinterpret_cast<const uint4*>(WL + (size_t)bn * KW + k0 / 2)[bw >> 2];
        }

        uint32_t ah[2][4], al[2][4];
#pragma unroll
        for (int mt = 0; mt < 2; mt++) {
            int r0 = warp_m * 32 + mt * 16 + qrow;
            ah[mt][0] = Ash[(r0    ) * AS_STRIDE + qcol    ];
            ah[mt][1] = Ash[(r0 + 8) * AS_STRIDE + qcol    ];
            ah[mt][2] = Ash[(r0    ) * AS_STRIDE + qcol + 4];
            ah[mt][3] = Ash[(r0 + 8) * AS_STRIDE + qcol + 4];
            al[mt][0] = Asl[(r0    ) * AS_STRIDE + qcol    ];
            al[mt][1] = Asl[(r0 + 8) * AS_STRIDE + qcol    ];
            al[mt][2] = Asl[(r0    ) * AS_STRIDE + qcol + 4];
            al[mt][3] = Asl[(r0 + 8) * AS_STRIDE + qcol + 4];
        }
#pragma unroll
        for (int nt = 0; nt < 8; nt++) {
            int n = warp_n * 64 + nt * 8 + qrow;
            uint32_t bh[2], bl[2];
            bh[0] = Bsh[n * BS_STRIDE + qcol    ];
            bh[1] = Bsh[n * BS_STRIDE + qcol + 4];
            bl[0] = Bsl[n * BS_STRIDE + qcol    ];
            bl[1] = Bsl[n * BS_STRIDE + qcol + 4];
#pragma unroll
            for (int mt = 0; mt < 2; mt++) {
                mma_bf16(acc[mt][nt], ah[mt], bl);
                mma_bf16(acc[mt][nt], al[mt], bh);
                mma_bf16(acc[mt][nt], ah[mt], bh);
            }
        }
        __syncthreads();
    }

    // Epilogue: pack fp32 pairs -> fp16x2 words into g_hs16 (64 words/row)
#pragma unroll
    for (int mt = 0; mt < 2; mt++) {
        int r0 = block_row + warp_m * 32 + mt * 16 + qrow;
        int r1 = r0 + 8;
#pragma unroll
        for (int nt = 0; nt < 8; nt++) {
            int cw = warp_n * 32 + nt * 4 + qcol;   // (c/2) word index
            if (r0 < M)
                g_hs16[(size_t)r0 * 64 + cw] = pack_f16x2(acc[mt][nt][0], acc[mt][nt][1]);
            if (r1 < M)
                g_hs16[(size_t)r1 * 64 + cw] = pack_f16x2(acc[mt][nt][2], acc[mt][nt][3]);
        }
    }
}

// ---------------------------------------------------------------------------
// CSR gather (fp16 rows) + dis weighting + fused finalize: one warp per node.
//   out[i] = dis[i] * ( dis[i]*h[i] + Σ dis[s]*h[s] ) + b     (+relu)
// Each lane reads one uint2 (4 fp16 features) per row -> 256B coalesced/warp.
// ---------------------------------------------------------------------------
template <bool RELU, bool WRITE_X1>
__global__ __launch_bounds__(256) void k_gather(
    const float* __restrict__ b, float* __restrict__ out_arg,
    int node_off, int node_end)
{
    float* __restrict__ out = WRITE_X1 ? (float*)g_x1 : out_arg;
    const uint2* __restrict__ hsrow = reinterpret_cast<const uint2*>(g_hs16);

    int w    = node_off + ((blockIdx.x * 256 + threadIdx.x) >> 5);
    int lane = threadIdx.x & 31;
    if (w >= node_end) return;

    int start = g_rowptr[w];
    int end   = g_rowptr[w + 1];
    float dw  = g_dis[w];

    // self loop: dis[w] * h[w]
    uint2 sw = hsrow[(size_t)w * 32 + lane];
    float2 s0 = unpack_f16x2(sw.x);
    float2 s1 = unpack_f16x2(sw.y);
    float4 acc = make_float4(s0.x * dw, s0.y * dw, s1.x * dw, s1.y * dw);

    for (int chunk = start; chunk < end; chunk += 32) {
        int remaining = end - chunk;
        int cnt   = remaining < 32 ? remaining : 32;
        int   myidx = (lane < cnt) ? g_csr[chunk + lane] : 0;
        float myds  = (lane < cnt) ? g_dis[myidx] : 0.f;
#pragma unroll 4
        for (int j = 0; j < cnt; j++) {
            int   s  = __shfl_sync(0xffffffffu, myidx, j);
            float ds = __shfl_sync(0xffffffffu, myds,  j);
            uint2 rw = hsrow[(size_t)s * 32 + lane];
            float2 p0 = unpack_f16x2(rw.x);
            float2 p1 = unpack_f16x2(rw.y);
            acc.x = fmaf(ds, p0.x, acc.x);
            acc.y = fmaf(ds, p0.y, acc.y);
            acc.z = fmaf(ds, p1.x, acc.z);
            acc.w = fmaf(ds, p1.y, acc.w);
        }
    }

    float4 bb = reinterpret_cast<const float4*>(b)[lane];
    float4 r;
    r.x = fmaf(dw, acc.x, bb.x);
    r.y = fmaf(dw, acc.y, bb.y);
    r.z = fmaf(dw, acc.z, bb.z);
    r.w = fmaf(dw, acc.w, bb.w);
    if (RELU) {
        r.x = fmaxf(r.x, 0.f); r.y = fmaxf(r.y, 0.f);
        r.z = fmaxf(r.z, 0.f); r.w = fmaxf(r.w, 0.f);
    }
    reinterpret_cast<float4*>(out + (size_t)w * 128)[lane] = r;
}

// ---------------------------------------------------------------------------
extern "C" void kernel_launch(void* const* d_in, const int* in_sizes, int n_in,
                              void* d_out, int out_size)
{
    const float* x  = (const float*)d_in[0];
    const int*   ei = (const int*)d_in[1];
    const float* W1 = (const float*)d_in[2];
    const float* b1 = (const float*)d_in[3];
    const float* W2 = (const float*)d_in[4];
    const float* b2 = (const float*)d_in[5];
    float*       out = (float*)d_out;

    const int M = in_sizes[0] / DIN;       // 50000
    const int E = in_sizes[1] / 2;         // 800000

    const int nblk   = (M + 255) / 256;
    const int eblk   = (E + 255) / 256;
    const int gemm_g = (M + 127) / 128;            // 391
    const int Ga     = (gemm_g + 1) / 2;           // 196
    const int Gb     = gemm_g - Ga;                // 195
    const int SPLIT  = Ga * 128;                   // 25088
    const int ga_g   = (SPLIT * 32 + 255) / 256;
    const int gb_g   = ((M - SPLIT) * 32 + 255) / 256;
    const int gath_g = (M * 32 + 255) / 256;

    static cudaStream_t s2 = nullptr;
    static cudaEvent_t  e_fork = nullptr, e_g1 = nullptr, e_csr = nullptr, e_b = nullptr;
    if (!s2) {
        cudaStreamCreateWithFlags(&s2, cudaStreamNonBlocking);
        cudaEventCreateWithFlags(&e_fork, cudaEventDisableTiming);
        cudaEventCreateWithFlags(&e_g1,   cudaEventDisableTiming);
        cudaEventCreateWithFlags(&e_csr,  cudaEventDisableTiming);
        cudaEventCreateWithFlags(&e_b,    cudaEventDisableTiming);
    }

    // Fork: side stream = weight prep + GEMM1 (independent of CSR/dis)
    cudaEventRecord(e_fork, 0);
    cudaStreamWaitEvent(s2, e_fork, 0);
    k_prep<<<64, 256, 0, s2>>>(W1, W2);
    k_gemm_bf16<DIN, false><<<gemm_g, 256, 0, s2>>>(x, M, 0);
    cudaEventRecord(e_g1, s2);

    // Main stream: CSR build (+ dis)
    k_count<<<eblk, 256>>>(ei, E);
    k_blocksum<<<nblk, 256>>>(M);
    k_rowptr<<<nblk, 256>>>(M, E);
    k_fill<<<eblk, 256>>>(ei, E);
    cudaEventRecord(e_csr, 0);

    // Row-split pipeline: gather1 -> GEMM2, halves on two streams
    cudaStreamWaitEvent(0, e_g1, 0);
    cudaStreamWaitEvent(s2, e_csr, 0);

    k_gather<true, true><<<ga_g, 256>>>(b1, nullptr, 0, SPLIT);
    k_gemm_bf16<DH, true><<<Ga, 256>>>(x, M, 0);

    k_gather<true, true><<<gb_g, 256, 0, s2>>>(b1, nullptr, SPLIT, M);
    k_gemm_bf16<DH, true><<<Gb, 256, 0, s2>>>(x, M, Ga);
    cudaEventRecord(e_b, s2);

    // Join, then final gather into d_out
    cudaStreamWaitEvent(0, e_b, 0);
    k_gather<false, false><<<gath_g, 256>>>(b2, out, 0, M);
}